// round 12
// baseline (speedup 1.0000x reference)
#include <cuda_runtime.h>
#include <cuda_bf16.h>
#include <cuda_fp16.h>
#include <cstdint>

// Problem constants: B=4, C=512, CI=128, H=W=64, N=4096
#define PB  4
#define PC  512
#define PCI 128
#define PN  4096

typedef __nv_bfloat16 bf16;

// ---------------- scratch (~309 MB of __device__ globals) -------------------
__device__ __align__(256) float g_e[(size_t)PB * PN * PN];   // 268 MB: xt scratch -> energy -> fp16 attn
__device__ __align__(256) bf16  g_qh[(size_t)PB * PN * PCI]; // [b][i][ci] bf16 h/l
__device__ __align__(256) bf16  g_ql[(size_t)PB * PN * PCI];
__device__ __align__(256) bf16  g_kh[(size_t)PB * PN * PCI];
__device__ __align__(256) bf16  g_kl[(size_t)PB * PN * PCI];
__device__ __align__(256) bf16  g_vh[(size_t)PB * PCI * PN]; // [b][ci][j] fp16 h/l bit patterns
__device__ __align__(256) bf16  g_vl[(size_t)PB * PCI * PN];
__device__ __align__(256) bf16  g_oh[(size_t)PB * PN * PCI]; // [b][i][ci] bf16 h/l
__device__ __align__(256) bf16  g_ol[(size_t)PB * PN * PCI];
__device__ __align__(256) bf16  g_wqh[PCI * PC], g_wql[PCI * PC];
__device__ __align__(256) bf16  g_wkh[PCI * PC], g_wkl[PCI * PC];
__device__ __align__(256) bf16  g_wvh[PCI * PC], g_wvl[PCI * PC];
__device__ __align__(256) bf16  g_woh[PC * PCI], g_wol[PC * PCI];

// ----------------------------------------------------------------------------
// Tensor-core GEMM, hi/lo split, cp.async double-buffered:
//   C[b][m][n] = sum_k A[b][m][k] * B[b][n][k]
// OMODE: 0 = fp32 out (+res), 1 = bf16 h/l out, 2 = fp16 h/l out
// BMODE: 0 = none, 1 = bias[m], 2 = bias[n]
// TERMS: 3 = ah*bh + ah*bl + al*bh ; 2 = ah*bh + ah*bl (A single precision)
// F16:   mma dtype f16 vs bf16
// ----------------------------------------------------------------------------
template<int BM, int BN, int WM, int WN, int OMODE, int BMODE, int TERMS, bool F16>
__global__ void __launch_bounds__(256)
mma_gemm3(const bf16* __restrict__ Ah, const bf16* __restrict__ Al,
          long long a_bs, int lda,
          const bf16* __restrict__ Bh, const bf16* __restrict__ Bl,
          long long b_bs, int ldb,
          float* __restrict__ C, bf16* __restrict__ Dh, bf16* __restrict__ Dl,
          long long c_bs, int ldc,
          const float* __restrict__ bias,
          const float* __restrict__ res, long long r_sb,
          int K)
{
    constexpr int BK  = 32;
    constexpr int LDS = 40;               // padded row stride; 80 B = 5*16 B
    constexpr int WARPS_M = BM / WM;
    constexpr int MT = WM / 16;
    constexpr int NT = WN / 8;
    constexpr int AROWS = (TERMS == 3) ? 2 * BM : BM;
    constexpr int SROWS = AROWS + 2 * BN;      // rows per stage
    constexpr int PASSES = (SROWS + 63) / 64;  // 256 thr, 4 thr/row (16B quads)
    constexpr int STG = SROWS * LDS;           // elems per stage

    extern __shared__ bf16 sm[];

    const int tid  = threadIdx.x;
    const int warp = tid >> 5;
    const int lane = tid & 31;
    const int wm = (warp % WARPS_M) * WM;
    const int wn = (warp / WARPS_M) * WN;

    const long long m0 = (long long)blockIdx.y * BM;
    const long long n0 = (long long)blockIdx.x * BN;
    const bf16* Abh = Ah + blockIdx.z * a_bs + m0 * lda;
    const bf16* Abl = Al + blockIdx.z * a_bs + m0 * lda;
    const bf16* Bbh = Bh + blockIdx.z * b_bs + n0 * ldb;
    const bf16* Bbl = Bl + blockIdx.z * b_bs + n0 * ldb;

    float acc[MT][NT][4];
#pragma unroll
    for (int i = 0; i < MT; i++)
#pragma unroll
        for (int j = 0; j < NT; j++)
#pragma unroll
            for (int r = 0; r < 4; r++) acc[i][j][r] = 0.0f;

    const int a_row = lane & 15, a_kh = (lane >> 4) << 3;
    const int b_row = (lane & 7) + ((lane >> 4) << 3), b_kh = lane & 8;

    // ---- cp.async loader: thread -> (row, 16B quad) ----
    const int lrow = tid >> 2;            // 0..63
    const int lq8  = (tid & 3) << 3;      // quad offset in elems (0,8,16,24)

    auto issue = [&](int stage, int kt) {
#pragma unroll
        for (int p = 0; p < PASSES; p++) {
            int r = lrow + p * 64;
            if (r < SROWS) {
                const bf16* src;
                if (r < BM)                 src = Abh + (long long)r * lda + kt + lq8;
                else if (r < AROWS)         src = Abl + (long long)(r - BM) * lda + kt + lq8;
                else if (r < AROWS + BN)    src = Bbh + (long long)(r - AROWS) * ldb + kt + lq8;
                else                        src = Bbl + (long long)(r - AROWS - BN) * ldb + kt + lq8;
                uint32_t dst = (uint32_t)__cvta_generic_to_shared(&sm[(size_t)stage * STG + r * LDS + lq8]);
                asm volatile("cp.async.cg.shared.global [%0], [%1], 16;" :: "r"(dst), "l"(src));
            }
        }
        asm volatile("cp.async.commit_group;");
    };

    issue(0, 0);
    int cur = 0;

    for (int kt = 0; kt < K; kt += BK) {
        const bool has_next = (kt + BK < K);
        if (has_next) {
            issue(cur ^ 1, kt + BK);
            asm volatile("cp.async.wait_group 1;");
        } else {
            asm volatile("cp.async.wait_group 0;");
        }
        __syncthreads();

        bf16* sAh = sm + (size_t)cur * STG;
        bf16* sAl = sAh + BM * LDS;                 // valid only if TERMS==3
        bf16* sBh = sAh + AROWS * LDS;
        bf16* sBl = sBh + BN * LDS;

#pragma unroll
        for (int ks = 0; ks < 2; ks++) {
            const int kc = ks * 16;
            uint32_t afh[MT][4], afl[MT][4];
#pragma unroll
            for (int mt = 0; mt < MT; mt++) {
                uint32_t ah_ = (uint32_t)__cvta_generic_to_shared(&sAh[(wm + mt*16 + a_row) * LDS + kc + a_kh]);
                asm volatile("ldmatrix.sync.aligned.m8n8.x4.shared.b16 {%0,%1,%2,%3}, [%4];"
                    : "=r"(afh[mt][0]), "=r"(afh[mt][1]), "=r"(afh[mt][2]), "=r"(afh[mt][3]) : "r"(ah_));
                if (TERMS == 3) {
                    uint32_t al_ = (uint32_t)__cvta_generic_to_shared(&sAl[(wm + mt*16 + a_row) * LDS + kc + a_kh]);
                    asm volatile("ldmatrix.sync.aligned.m8n8.x4.shared.b16 {%0,%1,%2,%3}, [%4];"
                        : "=r"(afl[mt][0]), "=r"(afl[mt][1]), "=r"(afl[mt][2]), "=r"(afl[mt][3]) : "r"(al_));
                }
            }
            uint32_t bfh[NT][2], bfl[NT][2];
#pragma unroll
            for (int jt = 0; jt < NT; jt += 2) {
                uint32_t bh_ = (uint32_t)__cvta_generic_to_shared(&sBh[(wn + jt*8 + b_row) * LDS + kc + b_kh]);
                uint32_t bl_ = (uint32_t)__cvta_generic_to_shared(&sBl[(wn + jt*8 + b_row) * LDS + kc + b_kh]);
                asm volatile("ldmatrix.sync.aligned.m8n8.x4.shared.b16 {%0,%1,%2,%3}, [%4];"
                    : "=r"(bfh[jt][0]), "=r"(bfh[jt][1]), "=r"(bfh[jt+1][0]), "=r"(bfh[jt+1][1]) : "r"(bh_));
                asm volatile("ldmatrix.sync.aligned.m8n8.x4.shared.b16 {%0,%1,%2,%3}, [%4];"
                    : "=r"(bfl[jt][0]), "=r"(bfl[jt][1]), "=r"(bfl[jt+1][0]), "=r"(bfl[jt+1][1]) : "r"(bl_));
            }
#pragma unroll
            for (int mt = 0; mt < MT; mt++)
#pragma unroll
                for (int jt = 0; jt < NT; jt++) {
                    float* d = acc[mt][jt];
#define MMA_T(A0,A1,A2,A3,B0,B1)                                                  \
    if (F16)                                                                      \
        asm volatile("mma.sync.aligned.m16n8k16.row.col.f32.f16.f16.f32 "        \
            "{%0,%1,%2,%3}, {%4,%5,%6,%7}, {%8,%9}, {%0,%1,%2,%3};"              \
            : "+f"(d[0]), "+f"(d[1]), "+f"(d[2]), "+f"(d[3])                     \
            : "r"(A0), "r"(A1), "r"(A2), "r"(A3), "r"(B0), "r"(B1));             \
    else                                                                          \
        asm volatile("mma.sync.aligned.m16n8k16.row.col.f32.bf16.bf16.f32 "      \
            "{%0,%1,%2,%3}, {%4,%5,%6,%7}, {%8,%9}, {%0,%1,%2,%3};"              \
            : "+f"(d[0]), "+f"(d[1]), "+f"(d[2]), "+f"(d[3])                     \
            : "r"(A0), "r"(A1), "r"(A2), "r"(A3), "r"(B0), "r"(B1))
                    MMA_T(afh[mt][0], afh[mt][1], afh[mt][2], afh[mt][3], bfh[jt][0], bfh[jt][1]);
                    MMA_T(afh[mt][0], afh[mt][1], afh[mt][2], afh[mt][3], bfl[jt][0], bfl[jt][1]);
                    if (TERMS == 3)
                        MMA_T(afl[mt][0], afl[mt][1], afl[mt][2], afl[mt][3], bfh[jt][0], bfh[jt][1]);
#undef MMA_T
                }
        }
        __syncthreads();
        cur ^= 1;
    }

    // ---- epilogue ----
    const int cr = lane >> 2, cc = (lane & 3) << 1;
    if (OMODE == 0) {
        float* Cb = C + blockIdx.z * c_bs;
        const float* Rb = res ? res + blockIdx.z * r_sb : nullptr;
#pragma unroll
        for (int mt = 0; mt < MT; mt++)
#pragma unroll
            for (int jt = 0; jt < NT; jt++) {
#pragma unroll
                for (int half = 0; half < 2; half++) {
                    long long row = m0 + wm + mt*16 + cr + half*8;
                    long long col = n0 + wn + jt*8 + cc;
                    float v0 = acc[mt][jt][half*2 + 0];
                    float v1 = acc[mt][jt][half*2 + 1];
                    if (BMODE == 1) { float bv = bias[row]; v0 += bv; v1 += bv; }
                    else if (BMODE == 2) { v0 += bias[col]; v1 += bias[col + 1]; }
                    if (Rb) {
                        const float2 rv = *(const float2*)&Rb[row * ldc + col];
                        v0 += rv.x; v1 += rv.y;
                    }
                    *(float2*)&Cb[row * ldc + col] = make_float2(v0, v1);
                }
            }
    } else if (OMODE == 1) {
        bf16* DhB = Dh + blockIdx.z * c_bs;
        bf16* DlB = Dl + blockIdx.z * c_bs;
#pragma unroll
        for (int mt = 0; mt < MT; mt++)
#pragma unroll
            for (int jt = 0; jt < NT; jt++) {
#pragma unroll
                for (int half = 0; half < 2; half++) {
                    long long row = m0 + wm + mt*16 + cr + half*8;
                    long long col = n0 + wn + jt*8 + cc;
                    float v0 = acc[mt][jt][half*2 + 0];
                    float v1 = acc[mt][jt][half*2 + 1];
                    if (BMODE == 1) { float bv = bias[row]; v0 += bv; v1 += bv; }
                    else if (BMODE == 2) { v0 += bias[col]; v1 += bias[col + 1]; }
                    bf16 h0 = __float2bfloat16_rn(v0);
                    bf16 h1 = __float2bfloat16_rn(v1);
                    __nv_bfloat162 hp; hp.x = h0; hp.y = h1;
                    __nv_bfloat162 lp;
                    lp.x = __float2bfloat16_rn(v0 - __bfloat162float(h0));
                    lp.y = __float2bfloat16_rn(v1 - __bfloat162float(h1));
                    *(__nv_bfloat162*)&DhB[row * ldc + col] = hp;
                    *(__nv_bfloat162*)&DlB[row * ldc + col] = lp;
                }
            }
    } else {
        __half* DhB = (__half*)(Dh + blockIdx.z * c_bs);
        __half* DlB = (__half*)(Dl + blockIdx.z * c_bs);
#pragma unroll
        for (int mt = 0; mt < MT; mt++)
#pragma unroll
            for (int jt = 0; jt < NT; jt++) {
#pragma unroll
                for (int half = 0; half < 2; half++) {
                    long long row = m0 + wm + mt*16 + cr + half*8;
                    long long col = n0 + wn + jt*8 + cc;
                    float v0 = acc[mt][jt][half*2 + 0];
                    float v1 = acc[mt][jt][half*2 + 1];
                    if (BMODE == 1) { float bv = bias[row]; v0 += bv; v1 += bv; }
                    else if (BMODE == 2) { v0 += bias[col]; v1 += bias[col + 1]; }
                    __half h0 = __float2half_rn(v0);
                    __half h1 = __float2half_rn(v1);
                    __half2 hp; hp.x = h0; hp.y = h1;
                    __half2 lp;
                    lp.x = __float2half_rn(v0 - __half2float(h0));
                    lp.y = __float2half_rn(v1 - __half2float(h1));
                    *(__half2*)&DhB[row * ldc + col] = hp;
                    *(__half2*)&DlB[row * ldc + col] = lp;
                }
            }
    }
}

// ----------------------------------------------------------------------------
// Transpose + hi/lo split: src fp32 [b][R][N] -> dh/dl bf16 [b][N][R]
// ----------------------------------------------------------------------------
__global__ void __launch_bounds__(256)
tsplit(const float* __restrict__ src, bf16* __restrict__ dh, bf16* __restrict__ dl, int R)
{
    __shared__ float t[32][33];
    const int tx = threadIdx.x, ty = threadIdx.y;           // 32 x 8
    const long long b = blockIdx.z;
    const int n0 = blockIdx.x * 32, r0 = blockIdx.y * 32;
    const float* S = src + b * (long long)R * PN;
#pragma unroll
    for (int i = 0; i < 4; i++)
        t[ty + i*8][tx] = S[(long long)(r0 + ty + i*8) * PN + n0 + tx];
    __syncthreads();
    bf16* DH = dh + b * (long long)R * PN;
    bf16* DL = dl + b * (long long)R * PN;
#pragma unroll
    for (int i = 0; i < 4; i++) {
        float v = t[tx][ty + i*8];
        bf16 h = __float2bfloat16_rn(v);
        long long off = (long long)(n0 + ty + i*8) * R + r0 + tx;
        DH[off] = h;
        DL[off] = __float2bfloat16_rn(v - __bfloat162float(h));
    }
}

// Four weight splits in one launch (all 65536 elements); blockIdx.y selects.
__global__ void __launch_bounds__(256)
esplit4(const float* s0, const float* s1, const float* s2, const float* s3,
        bf16* h0, bf16* h1, bf16* h2, bf16* h3,
        bf16* l0, bf16* l1, bf16* l2, bf16* l3)
{
    const float* s; bf16* dh; bf16* dl;
    switch (blockIdx.y) {
        case 0: s = s0; dh = h0; dl = l0; break;
        case 1: s = s1; dh = h1; dl = l1; break;
        case 2: s = s2; dh = h2; dl = l2; break;
        default: s = s3; dh = h3; dl = l3; break;
    }
    int i = blockIdx.x * 256 + threadIdx.x;
    float v = s[i];
    bf16 h = __float2bfloat16_rn(v);
    dh[i] = h;
    dl[i] = __float2bfloat16_rn(v - __bfloat162float(h));
}

// ----------------------------------------------------------------------------
// Row softmax (N=4096), IN PLACE, vectorized; writes single fp16 attn row.
// ----------------------------------------------------------------------------
__global__ void __launch_bounds__(256)
softmax_split_inplace(float* __restrict__ e)
{
    float* p = e + (size_t)blockIdx.x * PN;
    const int tid = threadIdx.x;
    const int warp = tid >> 5, lane = tid & 31;

    const float4* p4 = (const float4*)p;
    float4 v[4];
    float mx = -1e30f;
#pragma unroll
    for (int i = 0; i < 4; i++) {
        v[i] = p4[tid + i * 256];
        mx = fmaxf(mx, fmaxf(fmaxf(v[i].x, v[i].y), fmaxf(v[i].z, v[i].w)));
    }
#pragma unroll
    for (int o = 16; o > 0; o >>= 1) mx = fmaxf(mx, __shfl_xor_sync(0xffffffffu, mx, o));

    __shared__ float red[8];
    if (lane == 0) red[warp] = mx;
    __syncthreads();
#pragma unroll
    for (int i = 0; i < 8; i++) mx = fmaxf(mx, red[i]);
    __syncthreads();

    float sum = 0.0f;
#pragma unroll
    for (int i = 0; i < 4; i++) {
        v[i].x = __expf(v[i].x - mx);
        v[i].y = __expf(v[i].y - mx);
        v[i].z = __expf(v[i].z - mx);
        v[i].w = __expf(v[i].w - mx);
        sum += (v[i].x + v[i].y) + (v[i].z + v[i].w);
    }
#pragma unroll
    for (int o = 16; o > 0; o >>= 1) sum += __shfl_xor_sync(0xffffffffu, sum, o);
    if (lane == 0) red[warp] = sum;
    __syncthreads();
    sum = 0.0f;
#pragma unroll
    for (int i = 0; i < 8; i++) sum += red[i];
    const float inv = 1.0f / sum;

    uint2* ph = (uint2*)p;
#pragma unroll
    for (int i = 0; i < 4; i++) {
        float r0 = v[i].x * inv, r1 = v[i].y * inv, r2 = v[i].z * inv, r3 = v[i].w * inv;
        __half2 ha; ha.x = __float2half_rn(r0); ha.y = __float2half_rn(r1);
        __half2 hb; hb.x = __float2half_rn(r2); hb.y = __float2half_rn(r3);
        uint2 hu;
        hu.x = *(uint32_t*)&ha; hu.y = *(uint32_t*)&hb;
        ph[tid + i * 256] = hu;
    }
}

// ----------------------------------------------------------------------------
// Launch
// ----------------------------------------------------------------------------
extern "C" void kernel_launch(void* const* d_in, const int* in_sizes, int n_in,
                              void* d_out, int out_size)
{
    (void)in_sizes; (void)n_in; (void)out_size;
    const float* x  = (const float*)d_in[0];
    const float* wq = (const float*)d_in[1];
    const float* bq = (const float*)d_in[2];
    const float* wk = (const float*)d_in[3];
    const float* bk = (const float*)d_in[4];
    const float* wv = (const float*)d_in[5];
    const float* bv = (const float*)d_in[6];
    const float* wo = (const float*)d_in[7];
    const float* bo = (const float*)d_in[8];
    float* out = (float*)d_out;

    // dynamic smem bytes: 2 stages * SROWS * LDS(=40) * 2B
    const int SM_QK  = 2 * (2*16  + 2*128) * 40 * 2;   // 46080 (16x128, TERMS=3)
    const int SM_PV  = 2 * (16    + 2*128) * 40 * 2;   // 43520 (16x128, TERMS=2)
    const int SM_E   = 2 * (2*128 + 2*128) * 40 * 2;   // 81920 (128x128, TERMS=3)
    const int SM_OP  = 2 * (2*64  + 2*128) * 40 * 2;   // 61440 (64x128, TERMS=3)

    static float *e = nullptr;
    static bf16 *xth,*xtl,*qh,*ql,*kh,*kl,*vh,*vl,*oh,*ol;
    static bf16 *wqh,*wql,*wkh,*wkl,*wvh,*wvl,*woh,*wol;
    if (!e) {
        cudaGetSymbolAddress((void**)&e,   g_e);
        cudaGetSymbolAddress((void**)&qh,  g_qh);
        cudaGetSymbolAddress((void**)&ql,  g_ql);
        cudaGetSymbolAddress((void**)&kh,  g_kh);
        cudaGetSymbolAddress((void**)&kl,  g_kl);
        cudaGetSymbolAddress((void**)&vh,  g_vh);
        cudaGetSymbolAddress((void**)&vl,  g_vl);
        cudaGetSymbolAddress((void**)&oh,  g_oh);
        cudaGetSymbolAddress((void**)&ol,  g_ol);
        cudaGetSymbolAddress((void**)&wqh, g_wqh);
        cudaGetSymbolAddress((void**)&wql, g_wql);
        cudaGetSymbolAddress((void**)&wkh, g_wkh);
        cudaGetSymbolAddress((void**)&wkl, g_wkl);
        cudaGetSymbolAddress((void**)&wvh, g_wvh);
        cudaGetSymbolAddress((void**)&wvl, g_wvl);
        cudaGetSymbolAddress((void**)&woh, g_woh);
        cudaGetSymbolAddress((void**)&wol, g_wol);
        xth = (bf16*)e;
        xtl = xth + (size_t)PB * PN * PC;
        cudaFuncSetAttribute(mma_gemm3<16,128,16,16,1,2,3,false>,
                             cudaFuncAttributeMaxDynamicSharedMemorySize, SM_QK);
        cudaFuncSetAttribute(mma_gemm3<16,128,16,16,2,1,3,false>,
                             cudaFuncAttributeMaxDynamicSharedMemorySize, SM_QK);
        cudaFuncSetAttribute(mma_gemm3<128,128,32,64,0,0,3,false>,
                             cudaFuncAttributeMaxDynamicSharedMemorySize, SM_E);
        cudaFuncSetAttribute(mma_gemm3<16,128,16,16,1,0,2,true>,
                             cudaFuncAttributeMaxDynamicSharedMemorySize, SM_PV);
        cudaFuncSetAttribute(mma_gemm3<64,128,32,32,0,1,3,false>,
                             cudaFuncAttributeMaxDynamicSharedMemorySize, SM_OP);
    }

    const long long N = PN, C = PC, CI = PCI;
    const long long xsb = C * N;
    const long long tsb = N * C;
    const long long qsb = N * CI;
    const long long vsb = CI * N;
    const long long esb = N * N;
    dim3 blk(256);

    // 0) split x (transposed, into g_e scratch) + weights (one launch)
    tsplit<<<dim3(PN/32, PC/32, PB), dim3(32,8)>>>(x, xth, xtl, PC);
    esplit4<<<dim3(PCI*PC/256, 4), blk>>>(wq, wk, wv, wo,
                                          wqh, wkh, wvh, woh,
                                          wql, wkl, wvl, wol);

    // 1) q,k: C[i][ci] = sum_c xt[i][c] * wq[ci][c]  (+bq per col) -> bf16 h/l
    mma_gemm3<16,128,16,16,1,2,3,false><<<dim3(1, PN/16, PB), blk, SM_QK>>>(
        xth, xtl, tsb, PC,  wqh, wql, 0, PC,
        nullptr, qh, ql, qsb, PCI,  bq, nullptr, 0, PC);
    mma_gemm3<16,128,16,16,1,2,3,false><<<dim3(1, PN/16, PB), blk, SM_QK>>>(
        xth, xtl, tsb, PC,  wkh, wkl, 0, PC,
        nullptr, kh, kl, qsb, PCI,  bk, nullptr, 0, PC);

    // 2) v: C[ci][j] = sum_c wv[ci][c] * xt[j][c]  (+bv per row) -> FP16 h/l
    mma_gemm3<16,128,16,16,2,1,3,false><<<dim3(PN/128, PCI/16, PB), blk, SM_QK>>>(
        wvh, wvl, 0, PC,  xth, xtl, tsb, PC,
        nullptr, vh, vl, vsb, PN,  bv, nullptr, 0, PC);

    // 3) energy[i][j] = sum_ci q[i][ci] k[j][ci]  -> fp32 (first writer of g_e)
    mma_gemm3<128,128,32,64,0,0,3,false><<<dim3(PN/128, PN/128, PB), blk, SM_E>>>(
        qh, ql, qsb, PCI,  kh, kl, qsb, PCI,
        e, nullptr, nullptr, esb, PN,  nullptr, nullptr, 0, PCI);

    // 4) softmax rows -> single fp16 attn row, packed in place
    softmax_split_inplace<<<PB * PN, blk>>>(e);

    // 5) O[i][ci] = sum_j attn[i][j] v[ci][j]  -> bf16 h/l  (fp16 mma, 2 terms)
    mma_gemm3<16,128,16,16,1,0,2,true><<<dim3(1, PN/16, PB), blk, SM_PV>>>(
        (const bf16*)e, (const bf16*)e, 2*esb, 2*PN,
        vh, vl, vsb, PN,
        nullptr, oh, ol, qsb, PCI,  nullptr, nullptr, 0, PN);

    // 6) out[c][n] = sum_ci wo[c][ci] * O[n][ci] + bo + x  -> fp32 d_out
    mma_gemm3<64,128,32,32,0,1,3,false><<<dim3(PN/128, PC/64, PB), blk, SM_OP>>>(
        woh, wol, 0, PCI,  oh, ol, qsb, PCI,
        out, nullptr, nullptr, xsb, PN,  bo, x, xsb, PCI);
}

// round 15
// speedup vs baseline: 1.3705x; 1.3705x over previous
#include <cuda_runtime.h>
#include <cuda_bf16.h>
#include <cuda_fp16.h>
#include <cstdint>

// Problem constants: B=4, C=512, CI=128, H=W=64, N=4096
#define PB  4
#define PC  512
#define PCI 128
#define PN  4096

typedef __nv_bfloat16 bf16;

// ---------------- scratch (~309 MB of __device__ globals) -------------------
__device__ __align__(256) float g_e[(size_t)PB * PN * PN];   // 268 MB: xt scratch -> energy -> fp16 attn
__device__ __align__(256) bf16  g_qh[(size_t)PB * PN * PCI]; // [b][i][ci] bf16 h/l
__device__ __align__(256) bf16  g_ql[(size_t)PB * PN * PCI];
__device__ __align__(256) bf16  g_kh[(size_t)PB * PN * PCI];
__device__ __align__(256) bf16  g_kl[(size_t)PB * PN * PCI];
__device__ __align__(256) bf16  g_vh[(size_t)PB * PCI * PN]; // [b][ci][j] fp16 h/l bit patterns
__device__ __align__(256) bf16  g_vl[(size_t)PB * PCI * PN];
__device__ __align__(256) bf16  g_oh[(size_t)PB * PN * PCI]; // [b][i][ci] bf16 h/l
__device__ __align__(256) bf16  g_ol[(size_t)PB * PN * PCI];
__device__ __align__(256) bf16  g_wqh[PCI * PC], g_wql[PCI * PC];
__device__ __align__(256) bf16  g_wkh[PCI * PC], g_wkl[PCI * PC];
__device__ __align__(256) bf16  g_wvh[PCI * PC], g_wvl[PCI * PC];
__device__ __align__(256) bf16  g_woh[PC * PCI], g_wol[PC * PCI];

// ----------------------------------------------------------------------------
// Tensor-core GEMM, hi/lo split, cp.async double-buffered:
//   C[b][m][n] = sum_k A[b][m][k] * B[b][n][k]
// OMODE: 0 = fp32 out (+res), 1 = bf16 h/l out, 2 = fp16 h/l out
// BMODE: 0 = none, 1 = bias[m], 2 = bias[n]
// TERMS: 3 = ah*bh + ah*bl + al*bh ; 2 = ah*bh + ah*bl (A single precision)
// F16:   mma dtype f16 vs bf16
// ----------------------------------------------------------------------------
template<int BM, int BN, int WM, int WN, int OMODE, int BMODE, int TERMS, bool F16>
__global__ void __launch_bounds__(256)
mma_gemm3(const bf16* __restrict__ Ah, const bf16* __restrict__ Al,
          long long a_bs, int lda,
          const bf16* __restrict__ Bh, const bf16* __restrict__ Bl,
          long long b_bs, int ldb,
          float* __restrict__ C, bf16* __restrict__ Dh, bf16* __restrict__ Dl,
          long long c_bs, int ldc,
          const float* __restrict__ bias,
          const float* __restrict__ res, long long r_sb,
          int K)
{
    constexpr int BK  = 32;
    constexpr int LDS = 40;               // padded row stride; 80 B = 5*16 B
    constexpr int WARPS_M = BM / WM;
    constexpr int MT = WM / 16;
    constexpr int NT = WN / 8;
    constexpr int AROWS = (TERMS == 3) ? 2 * BM : BM;
    constexpr int SROWS = AROWS + 2 * BN;      // rows per stage
    constexpr int PASSES = (SROWS + 63) / 64;  // 256 thr, 4 thr/row (16B quads)
    constexpr int STG = SROWS * LDS;           // elems per stage

    extern __shared__ bf16 sm[];

    const int tid  = threadIdx.x;
    const int warp = tid >> 5;
    const int lane = tid & 31;
    const int wm = (warp % WARPS_M) * WM;
    const int wn = (warp / WARPS_M) * WN;

    const long long m0 = (long long)blockIdx.y * BM;
    const long long n0 = (long long)blockIdx.x * BN;
    const bf16* Abh = Ah + blockIdx.z * a_bs + m0 * lda;
    const bf16* Abl = Al + blockIdx.z * a_bs + m0 * lda;
    const bf16* Bbh = Bh + blockIdx.z * b_bs + n0 * ldb;
    const bf16* Bbl = Bl + blockIdx.z * b_bs + n0 * ldb;

    float acc[MT][NT][4];
#pragma unroll
    for (int i = 0; i < MT; i++)
#pragma unroll
        for (int j = 0; j < NT; j++)
#pragma unroll
            for (int r = 0; r < 4; r++) acc[i][j][r] = 0.0f;

    const int a_row = lane & 15, a_kh = (lane >> 4) << 3;
    const int b_row = (lane & 7) + ((lane >> 4) << 3), b_kh = lane & 8;

    // ---- cp.async loader: thread -> (row, 16B quad) ----
    const int lrow = tid >> 2;            // 0..63
    const int lq8  = (tid & 3) << 3;      // quad offset in elems (0,8,16,24)

    auto issue = [&](int stage, int kt) {
#pragma unroll
        for (int p = 0; p < PASSES; p++) {
            int r = lrow + p * 64;
            if (r < SROWS) {
                const bf16* src;
                if (r < BM)                 src = Abh + (long long)r * lda + kt + lq8;
                else if (r < AROWS)         src = Abl + (long long)(r - BM) * lda + kt + lq8;
                else if (r < AROWS + BN)    src = Bbh + (long long)(r - AROWS) * ldb + kt + lq8;
                else                        src = Bbl + (long long)(r - AROWS - BN) * ldb + kt + lq8;
                uint32_t dst = (uint32_t)__cvta_generic_to_shared(&sm[(size_t)stage * STG + r * LDS + lq8]);
                asm volatile("cp.async.cg.shared.global [%0], [%1], 16;" :: "r"(dst), "l"(src));
            }
        }
        asm volatile("cp.async.commit_group;");
    };

    issue(0, 0);
    int cur = 0;

    for (int kt = 0; kt < K; kt += BK) {
        const bool has_next = (kt + BK < K);
        if (has_next) {
            issue(cur ^ 1, kt + BK);
            asm volatile("cp.async.wait_group 1;");
        } else {
            asm volatile("cp.async.wait_group 0;");
        }
        __syncthreads();

        bf16* sAh = sm + (size_t)cur * STG;
        bf16* sAl = sAh + BM * LDS;                 // valid only if TERMS==3
        bf16* sBh = sAh + AROWS * LDS;
        bf16* sBl = sBh + BN * LDS;

#pragma unroll
        for (int ks = 0; ks < 2; ks++) {
            const int kc = ks * 16;
            uint32_t afh[MT][4], afl[MT][4];
#pragma unroll
            for (int mt = 0; mt < MT; mt++) {
                uint32_t ah_ = (uint32_t)__cvta_generic_to_shared(&sAh[(wm + mt*16 + a_row) * LDS + kc + a_kh]);
                asm volatile("ldmatrix.sync.aligned.m8n8.x4.shared.b16 {%0,%1,%2,%3}, [%4];"
                    : "=r"(afh[mt][0]), "=r"(afh[mt][1]), "=r"(afh[mt][2]), "=r"(afh[mt][3]) : "r"(ah_));
                if (TERMS == 3) {
                    uint32_t al_ = (uint32_t)__cvta_generic_to_shared(&sAl[(wm + mt*16 + a_row) * LDS + kc + a_kh]);
                    asm volatile("ldmatrix.sync.aligned.m8n8.x4.shared.b16 {%0,%1,%2,%3}, [%4];"
                        : "=r"(afl[mt][0]), "=r"(afl[mt][1]), "=r"(afl[mt][2]), "=r"(afl[mt][3]) : "r"(al_));
                }
            }
            uint32_t bfh[NT][2], bfl[NT][2];
#pragma unroll
            for (int jt = 0; jt < NT; jt += 2) {
                uint32_t bh_ = (uint32_t)__cvta_generic_to_shared(&sBh[(wn + jt*8 + b_row) * LDS + kc + b_kh]);
                uint32_t bl_ = (uint32_t)__cvta_generic_to_shared(&sBl[(wn + jt*8 + b_row) * LDS + kc + b_kh]);
                asm volatile("ldmatrix.sync.aligned.m8n8.x4.shared.b16 {%0,%1,%2,%3}, [%4];"
                    : "=r"(bfh[jt][0]), "=r"(bfh[jt][1]), "=r"(bfh[jt+1][0]), "=r"(bfh[jt+1][1]) : "r"(bh_));
                asm volatile("ldmatrix.sync.aligned.m8n8.x4.shared.b16 {%0,%1,%2,%3}, [%4];"
                    : "=r"(bfl[jt][0]), "=r"(bfl[jt][1]), "=r"(bfl[jt+1][0]), "=r"(bfl[jt+1][1]) : "r"(bl_));
            }
#pragma unroll
            for (int mt = 0; mt < MT; mt++)
#pragma unroll
                for (int jt = 0; jt < NT; jt++) {
                    float* d = acc[mt][jt];
#define MMA_T(A0,A1,A2,A3,B0,B1)                                                  \
    if (F16)                                                                      \
        asm volatile("mma.sync.aligned.m16n8k16.row.col.f32.f16.f16.f32 "        \
            "{%0,%1,%2,%3}, {%4,%5,%6,%7}, {%8,%9}, {%0,%1,%2,%3};"              \
            : "+f"(d[0]), "+f"(d[1]), "+f"(d[2]), "+f"(d[3])                     \
            : "r"(A0), "r"(A1), "r"(A2), "r"(A3), "r"(B0), "r"(B1));             \
    else                                                                          \
        asm volatile("mma.sync.aligned.m16n8k16.row.col.f32.bf16.bf16.f32 "      \
            "{%0,%1,%2,%3}, {%4,%5,%6,%7}, {%8,%9}, {%0,%1,%2,%3};"              \
            : "+f"(d[0]), "+f"(d[1]), "+f"(d[2]), "+f"(d[3])                     \
            : "r"(A0), "r"(A1), "r"(A2), "r"(A3), "r"(B0), "r"(B1))
                    MMA_T(afh[mt][0], afh[mt][1], afh[mt][2], afh[mt][3], bfh[jt][0], bfh[jt][1]);
                    MMA_T(afh[mt][0], afh[mt][1], afh[mt][2], afh[mt][3], bfl[jt][0], bfl[jt][1]);
                    if (TERMS == 3)
                        MMA_T(afl[mt][0], afl[mt][1], afl[mt][2], afl[mt][3], bfh[jt][0], bfh[jt][1]);
#undef MMA_T
                }
        }
        __syncthreads();
        cur ^= 1;
    }

    // ---- epilogue ----
    const int cr = lane >> 2, cc = (lane & 3) << 1;
    if (OMODE == 0) {
        float* Cb = C + blockIdx.z * c_bs;
        const float* Rb = res ? res + blockIdx.z * r_sb : nullptr;
#pragma unroll
        for (int mt = 0; mt < MT; mt++)
#pragma unroll
            for (int jt = 0; jt < NT; jt++) {
#pragma unroll
                for (int half = 0; half < 2; half++) {
                    long long row = m0 + wm + mt*16 + cr + half*8;
                    long long col = n0 + wn + jt*8 + cc;
                    float v0 = acc[mt][jt][half*2 + 0];
                    float v1 = acc[mt][jt][half*2 + 1];
                    if (BMODE == 1) { float bv = bias[row]; v0 += bv; v1 += bv; }
                    else if (BMODE == 2) { v0 += bias[col]; v1 += bias[col + 1]; }
                    if (Rb) {
                        const float2 rv = *(const float2*)&Rb[row * ldc + col];
                        v0 += rv.x; v1 += rv.y;
                    }
                    *(float2*)&Cb[row * ldc + col] = make_float2(v0, v1);
                }
            }
    } else if (OMODE == 1) {
        bf16* DhB = Dh + blockIdx.z * c_bs;
        bf16* DlB = Dl + blockIdx.z * c_bs;
#pragma unroll
        for (int mt = 0; mt < MT; mt++)
#pragma unroll
            for (int jt = 0; jt < NT; jt++) {
#pragma unroll
                for (int half = 0; half < 2; half++) {
                    long long row = m0 + wm + mt*16 + cr + half*8;
                    long long col = n0 + wn + jt*8 + cc;
                    float v0 = acc[mt][jt][half*2 + 0];
                    float v1 = acc[mt][jt][half*2 + 1];
                    if (BMODE == 1) { float bv = bias[row]; v0 += bv; v1 += bv; }
                    else if (BMODE == 2) { v0 += bias[col]; v1 += bias[col + 1]; }
                    bf16 h0 = __float2bfloat16_rn(v0);
                    bf16 h1 = __float2bfloat16_rn(v1);
                    __nv_bfloat162 hp; hp.x = h0; hp.y = h1;
                    __nv_bfloat162 lp;
                    lp.x = __float2bfloat16_rn(v0 - __bfloat162float(h0));
                    lp.y = __float2bfloat16_rn(v1 - __bfloat162float(h1));
                    *(__nv_bfloat162*)&DhB[row * ldc + col] = hp;
                    *(__nv_bfloat162*)&DlB[row * ldc + col] = lp;
                }
            }
    } else {
        __half* DhB = (__half*)(Dh + blockIdx.z * c_bs);
        __half* DlB = (__half*)(Dl + blockIdx.z * c_bs);
#pragma unroll
        for (int mt = 0; mt < MT; mt++)
#pragma unroll
            for (int jt = 0; jt < NT; jt++) {
#pragma unroll
                for (int half = 0; half < 2; half++) {
                    long long row = m0 + wm + mt*16 + cr + half*8;
                    long long col = n0 + wn + jt*8 + cc;
                    float v0 = acc[mt][jt][half*2 + 0];
                    float v1 = acc[mt][jt][half*2 + 1];
                    if (BMODE == 1) { float bv = bias[row]; v0 += bv; v1 += bv; }
                    else if (BMODE == 2) { v0 += bias[col]; v1 += bias[col + 1]; }
                    __half h0 = __float2half_rn(v0);
                    __half h1 = __float2half_rn(v1);
                    __half2 hp; hp.x = h0; hp.y = h1;
                    __half2 lp;
                    lp.x = __float2half_rn(v0 - __half2float(h0));
                    lp.y = __float2half_rn(v1 - __half2float(h1));
                    *(__half2*)&DhB[row * ldc + col] = hp;
                    *(__half2*)&DlB[row * ldc + col] = lp;
                }
            }
    }
}

// ----------------------------------------------------------------------------
// Transpose + hi/lo split: src fp32 [b][R][N] -> dh/dl bf16 [b][N][R]
// ----------------------------------------------------------------------------
__global__ void __launch_bounds__(256)
tsplit(const float* __restrict__ src, bf16* __restrict__ dh, bf16* __restrict__ dl, int R)
{
    __shared__ float t[32][33];
    const int tx = threadIdx.x, ty = threadIdx.y;           // 32 x 8
    const long long b = blockIdx.z;
    const int n0 = blockIdx.x * 32, r0 = blockIdx.y * 32;
    const float* S = src + b * (long long)R * PN;
#pragma unroll
    for (int i = 0; i < 4; i++)
        t[ty + i*8][tx] = S[(long long)(r0 + ty + i*8) * PN + n0 + tx];
    __syncthreads();
    bf16* DH = dh + b * (long long)R * PN;
    bf16* DL = dl + b * (long long)R * PN;
#pragma unroll
    for (int i = 0; i < 4; i++) {
        float v = t[tx][ty + i*8];
        bf16 h = __float2bfloat16_rn(v);
        long long off = (long long)(n0 + ty + i*8) * R + r0 + tx;
        DH[off] = h;
        DL[off] = __float2bfloat16_rn(v - __bfloat162float(h));
    }
}

// Elementwise hi/lo split (weights): fp32 -> bf16 h/l
__global__ void __launch_bounds__(256)
esplit(const float* __restrict__ src, bf16* __restrict__ dh, bf16* __restrict__ dl, int n)
{
    int i = blockIdx.x * 256 + threadIdx.x;
    if (i < n) {
        float v = src[i];
        bf16 h = __float2bfloat16_rn(v);
        dh[i] = h;
        dl[i] = __float2bfloat16_rn(v - __bfloat162float(h));
    }
}

// ----------------------------------------------------------------------------
// Row softmax (N=4096), IN PLACE, vectorized; writes single fp16 attn row.
// ----------------------------------------------------------------------------
__global__ void __launch_bounds__(256)
softmax_split_inplace(float* __restrict__ e)
{
    float* p = e + (size_t)blockIdx.x * PN;
    const int tid = threadIdx.x;
    const int warp = tid >> 5, lane = tid & 31;

    const float4* p4 = (const float4*)p;
    float4 v[4];
    float mx = -1e30f;
#pragma unroll
    for (int i = 0; i < 4; i++) {
        v[i] = p4[tid + i * 256];
        mx = fmaxf(mx, fmaxf(fmaxf(v[i].x, v[i].y), fmaxf(v[i].z, v[i].w)));
    }
#pragma unroll
    for (int o = 16; o > 0; o >>= 1) mx = fmaxf(mx, __shfl_xor_sync(0xffffffffu, mx, o));

    __shared__ float red[8];
    if (lane == 0) red[warp] = mx;
    __syncthreads();
#pragma unroll
    for (int i = 0; i < 8; i++) mx = fmaxf(mx, red[i]);
    __syncthreads();

    float sum = 0.0f;
#pragma unroll
    for (int i = 0; i < 4; i++) {
        v[i].x = __expf(v[i].x - mx);
        v[i].y = __expf(v[i].y - mx);
        v[i].z = __expf(v[i].z - mx);
        v[i].w = __expf(v[i].w - mx);
        sum += (v[i].x + v[i].y) + (v[i].z + v[i].w);
    }
#pragma unroll
    for (int o = 16; o > 0; o >>= 1) sum += __shfl_xor_sync(0xffffffffu, sum, o);
    if (lane == 0) red[warp] = sum;
    __syncthreads();
    sum = 0.0f;
#pragma unroll
    for (int i = 0; i < 8; i++) sum += red[i];
    const float inv = 1.0f / sum;

    uint2* ph = (uint2*)p;
#pragma unroll
    for (int i = 0; i < 4; i++) {
        float r0 = v[i].x * inv, r1 = v[i].y * inv, r2 = v[i].z * inv, r3 = v[i].w * inv;
        __half2 ha; ha.x = __float2half_rn(r0); ha.y = __float2half_rn(r1);
        __half2 hb; hb.x = __float2half_rn(r2); hb.y = __float2half_rn(r3);
        uint2 hu;
        hu.x = *(uint32_t*)&ha; hu.y = *(uint32_t*)&hb;
        ph[tid + i * 256] = hu;
    }
}

// ----------------------------------------------------------------------------
// Launch
// ----------------------------------------------------------------------------
extern "C" void kernel_launch(void* const* d_in, const int* in_sizes, int n_in,
                              void* d_out, int out_size)
{
    (void)in_sizes; (void)n_in; (void)out_size;
    const float* x  = (const float*)d_in[0];
    const float* wq = (const float*)d_in[1];
    const float* bq = (const float*)d_in[2];
    const float* wk = (const float*)d_in[3];
    const float* bk = (const float*)d_in[4];
    const float* wv = (const float*)d_in[5];
    const float* bv = (const float*)d_in[6];
    const float* wo = (const float*)d_in[7];
    const float* bo = (const float*)d_in[8];
    float* out = (float*)d_out;

    // dynamic smem bytes: 2 stages * SROWS * LDS(=40) * 2B
    const int SM_P3  = 2 * (2*64  + 2*128) * 40 * 2;   // 61440 (64x128, TERMS=3)
    const int SM_P2  = 2 * (64    + 2*128) * 40 * 2;   // 51200 (64x128, TERMS=2)
    const int SM_E   = 2 * (2*128 + 2*128) * 40 * 2;   // 81920 (128x128, TERMS=3)

    static float *e = nullptr;
    static bf16 *xth,*xtl,*qh,*ql,*kh,*kl,*vh,*vl,*oh,*ol;
    static bf16 *wqh,*wql,*wkh,*wkl,*wvh,*wvl,*woh,*wol;
    if (!e) {
        cudaGetSymbolAddress((void**)&e,   g_e);
        cudaGetSymbolAddress((void**)&qh,  g_qh);
        cudaGetSymbolAddress((void**)&ql,  g_ql);
        cudaGetSymbolAddress((void**)&kh,  g_kh);
        cudaGetSymbolAddress((void**)&kl,  g_kl);
        cudaGetSymbolAddress((void**)&vh,  g_vh);
        cudaGetSymbolAddress((void**)&vl,  g_vl);
        cudaGetSymbolAddress((void**)&oh,  g_oh);
        cudaGetSymbolAddress((void**)&ol,  g_ol);
        cudaGetSymbolAddress((void**)&wqh, g_wqh);
        cudaGetSymbolAddress((void**)&wql, g_wql);
        cudaGetSymbolAddress((void**)&wkh, g_wkh);
        cudaGetSymbolAddress((void**)&wkl, g_wkl);
        cudaGetSymbolAddress((void**)&wvh, g_wvh);
        cudaGetSymbolAddress((void**)&wvl, g_wvl);
        cudaGetSymbolAddress((void**)&woh, g_woh);
        cudaGetSymbolAddress((void**)&wol, g_wol);
        xth = (bf16*)e;
        xtl = xth + (size_t)PB * PN * PC;
        cudaFuncSetAttribute(mma_gemm3<64,128,32,32,1,2,3,false>,
                             cudaFuncAttributeMaxDynamicSharedMemorySize, SM_P3);
        cudaFuncSetAttribute(mma_gemm3<64,128,32,32,2,1,3,false>,
                             cudaFuncAttributeMaxDynamicSharedMemorySize, SM_P3);
        cudaFuncSetAttribute(mma_gemm3<128,128,32,64,0,0,3,false>,
                             cudaFuncAttributeMaxDynamicSharedMemorySize, SM_E);
        cudaFuncSetAttribute(mma_gemm3<64,128,32,32,1,0,2,true>,
                             cudaFuncAttributeMaxDynamicSharedMemorySize, SM_P2);
        cudaFuncSetAttribute(mma_gemm3<128,128,32,64,0,1,3,false>,
                             cudaFuncAttributeMaxDynamicSharedMemorySize, SM_E);
    }

    const long long N = PN, C = PC, CI = PCI;
    const long long xsb = C * N;
    const long long tsb = N * C;
    const long long qsb = N * CI;
    const long long vsb = CI * N;
    const long long esb = N * N;
    dim3 blk(256);

    // 0) split x (transposed, into g_e scratch) + weights
    tsplit<<<dim3(PN/32, PC/32, PB), dim3(32,8)>>>(x, xth, xtl, PC);
    esplit<<<PCI*PC/256, blk>>>(wq, wqh, wql, PCI*PC);
    esplit<<<PCI*PC/256, blk>>>(wk, wkh, wkl, PCI*PC);
    esplit<<<PCI*PC/256, blk>>>(wv, wvh, wvl, PCI*PC);
    esplit<<<PC*PCI/256, blk>>>(wo, woh, wol, PC*PCI);

    // 1) q,k: C[i][ci] = sum_c xt[i][c] * wq[ci][c]  (+bq per col) -> bf16 h/l
    mma_gemm3<64,128,32,32,1,2,3,false><<<dim3(1, PN/64, PB), blk, SM_P3>>>(
        xth, xtl, tsb, PC,  wqh, wql, 0, PC,
        nullptr, qh, ql, qsb, PCI,  bq, nullptr, 0, PC);
    mma_gemm3<64,128,32,32,1,2,3,false><<<dim3(1, PN/64, PB), blk, SM_P3>>>(
        xth, xtl, tsb, PC,  wkh, wkl, 0, PC,
        nullptr, kh, kl, qsb, PCI,  bk, nullptr, 0, PC);

    // 2) v: C[ci][j] = sum_c wv[ci][c] * xt[j][c]  (+bv per row) -> FP16 h/l
    mma_gemm3<64,128,32,32,2,1,3,false><<<dim3(PN/128, PCI/64, PB), blk, SM_P3>>>(
        wvh, wvl, 0, PC,  xth, xtl, tsb, PC,
        nullptr, vh, vl, vsb, PN,  bv, nullptr, 0, PC);

    // 3) energy[i][j] = sum_ci q[i][ci] k[j][ci]  -> fp32 (first writer of g_e)
    mma_gemm3<128,128,32,64,0,0,3,false><<<dim3(PN/128, PN/128, PB), blk, SM_E>>>(
        qh, ql, qsb, PCI,  kh, kl, qsb, PCI,
        e, nullptr, nullptr, esb, PN,  nullptr, nullptr, 0, PCI);

    // 4) softmax rows -> single fp16 attn row, packed in place
    softmax_split_inplace<<<PB * PN, blk>>>(e);

    // 5) O[i][ci] = sum_j attn[i][j] v[ci][j]  -> bf16 h/l  (fp16 mma, 2 terms)
    mma_gemm3<64,128,32,32,1,0,2,true><<<dim3(1, PN/64, PB), blk, SM_P2>>>(
        (const bf16*)e, (const bf16*)e, 2*esb, 2*PN,
        vh, vl, vsb, PN,
        nullptr, oh, ol, qsb, PCI,  nullptr, nullptr, 0, PN);

    // 6) out[c][n] = sum_ci wo[c][ci] * O[n][ci] + bo + x  -> fp32 d_out
    mma_gemm3<128,128,32,64,0,1,3,false><<<dim3(PN/128, PC/128, PB), blk, SM_E>>>(
        woh, wol, 0, PCI,  oh, ol, qsb, PCI,
        out, nullptr, nullptr, xsb, PN,  bo, x, xsb, PCI);
}

// round 16
// speedup vs baseline: 1.7772x; 1.2968x over previous
#include <cuda_runtime.h>
#include <cuda_bf16.h>
#include <cuda_fp16.h>
#include <cstdint>

// Problem constants: B=4, C=512, CI=128, H=W=64, N=4096
#define PB  4
#define PC  512
#define PCI 128
#define PN  4096

typedef __nv_bfloat16 bf16;

// ---------------- scratch (~75 MB of __device__ globals) --------------------
__device__ __align__(256) bf16  g_xth[(size_t)PB * PN * PC]; // x^T hi [b][n][c]
__device__ __align__(256) bf16  g_xtl[(size_t)PB * PN * PC];
__device__ __align__(256) bf16  g_qh[(size_t)PB * PN * PCI]; // [b][i][ci] bf16 h/l
__device__ __align__(256) bf16  g_ql[(size_t)PB * PN * PCI];
__device__ __align__(256) bf16  g_kh[(size_t)PB * PN * PCI];
__device__ __align__(256) bf16  g_kl[(size_t)PB * PN * PCI];
__device__ __align__(256) bf16  g_vh[(size_t)PB * PCI * PN]; // [b][ci][j] fp16 h/l bit patterns
__device__ __align__(256) bf16  g_vl[(size_t)PB * PCI * PN];
__device__ __align__(256) bf16  g_oh[(size_t)PB * PN * PCI]; // [b][i][ci] bf16 h/l
__device__ __align__(256) bf16  g_ol[(size_t)PB * PN * PCI];
__device__ __align__(256) bf16  g_wqh[PCI * PC], g_wql[PCI * PC];
__device__ __align__(256) bf16  g_wkh[PCI * PC], g_wkl[PCI * PC];
__device__ __align__(256) bf16  g_wvh[PCI * PC], g_wvl[PCI * PC];
__device__ __align__(256) bf16  g_woh[PC * PCI], g_wol[PC * PCI];

// ----------------------------------------------------------------------------
// Tensor-core GEMM, hi/lo split, cp.async double-buffered (projections/out-proj)
// OMODE: 0 = fp32 out (+res), 1 = bf16 h/l out, 2 = fp16 h/l out
// BMODE: 0 = none, 1 = bias[m], 2 = bias[n]
// TERMS: 3 = ah*bh + ah*bl + al*bh ; 2 = ah*bh + ah*bl
// ----------------------------------------------------------------------------
template<int BM, int BN, int WM, int WN, int OMODE, int BMODE, int TERMS, bool F16>
__global__ void __launch_bounds__(256)
mma_gemm3(const bf16* __restrict__ Ah, const bf16* __restrict__ Al,
          long long a_bs, int lda,
          const bf16* __restrict__ Bh, const bf16* __restrict__ Bl,
          long long b_bs, int ldb,
          float* __restrict__ C, bf16* __restrict__ Dh, bf16* __restrict__ Dl,
          long long c_bs, int ldc,
          const float* __restrict__ bias,
          const float* __restrict__ res, long long r_sb,
          int K)
{
    constexpr int BK  = 32;
    constexpr int LDS = 40;
    constexpr int WARPS_M = BM / WM;
    constexpr int MT = WM / 16;
    constexpr int NT = WN / 8;
    constexpr int AROWS = (TERMS == 3) ? 2 * BM : BM;
    constexpr int SROWS = AROWS + 2 * BN;
    constexpr int PASSES = (SROWS + 63) / 64;
    constexpr int STG = SROWS * LDS;

    extern __shared__ bf16 sm[];

    const int tid  = threadIdx.x;
    const int warp = tid >> 5;
    const int lane = tid & 31;
    const int wm = (warp % WARPS_M) * WM;
    const int wn = (warp / WARPS_M) * WN;

    const long long m0 = (long long)blockIdx.y * BM;
    const long long n0 = (long long)blockIdx.x * BN;
    const bf16* Abh = Ah + blockIdx.z * a_bs + m0 * lda;
    const bf16* Abl = Al + blockIdx.z * a_bs + m0 * lda;
    const bf16* Bbh = Bh + blockIdx.z * b_bs + n0 * ldb;
    const bf16* Bbl = Bl + blockIdx.z * b_bs + n0 * ldb;

    float acc[MT][NT][4];
#pragma unroll
    for (int i = 0; i < MT; i++)
#pragma unroll
        for (int j = 0; j < NT; j++)
#pragma unroll
            for (int r = 0; r < 4; r++) acc[i][j][r] = 0.0f;

    const int a_row = lane & 15, a_kh = (lane >> 4) << 3;
    const int b_row = (lane & 7) + ((lane >> 4) << 3), b_kh = lane & 8;

    const int lrow = tid >> 2;
    const int lq8  = (tid & 3) << 3;

    auto issue = [&](int stage, int kt) {
#pragma unroll
        for (int p = 0; p < PASSES; p++) {
            int r = lrow + p * 64;
            if (r < SROWS) {
                const bf16* src;
                if (r < BM)                 src = Abh + (long long)r * lda + kt + lq8;
                else if (r < AROWS)         src = Abl + (long long)(r - BM) * lda + kt + lq8;
                else if (r < AROWS + BN)    src = Bbh + (long long)(r - AROWS) * ldb + kt + lq8;
                else                        src = Bbl + (long long)(r - AROWS - BN) * ldb + kt + lq8;
                uint32_t dst = (uint32_t)__cvta_generic_to_shared(&sm[(size_t)stage * STG + r * LDS + lq8]);
                asm volatile("cp.async.cg.shared.global [%0], [%1], 16;" :: "r"(dst), "l"(src));
            }
        }
        asm volatile("cp.async.commit_group;");
    };

    issue(0, 0);
    int cur = 0;

    for (int kt = 0; kt < K; kt += BK) {
        const bool has_next = (kt + BK < K);
        if (has_next) {
            issue(cur ^ 1, kt + BK);
            asm volatile("cp.async.wait_group 1;");
        } else {
            asm volatile("cp.async.wait_group 0;");
        }
        __syncthreads();

        bf16* sAh = sm + (size_t)cur * STG;
        bf16* sAl = sAh + BM * LDS;
        bf16* sBh = sAh + AROWS * LDS;
        bf16* sBl = sBh + BN * LDS;

#pragma unroll
        for (int ks = 0; ks < 2; ks++) {
            const int kc = ks * 16;
            uint32_t afh[MT][4], afl[MT][4];
#pragma unroll
            for (int mt = 0; mt < MT; mt++) {
                uint32_t ah_ = (uint32_t)__cvta_generic_to_shared(&sAh[(wm + mt*16 + a_row) * LDS + kc + a_kh]);
                asm volatile("ldmatrix.sync.aligned.m8n8.x4.shared.b16 {%0,%1,%2,%3}, [%4];"
                    : "=r"(afh[mt][0]), "=r"(afh[mt][1]), "=r"(afh[mt][2]), "=r"(afh[mt][3]) : "r"(ah_));
                if (TERMS == 3) {
                    uint32_t al_ = (uint32_t)__cvta_generic_to_shared(&sAl[(wm + mt*16 + a_row) * LDS + kc + a_kh]);
                    asm volatile("ldmatrix.sync.aligned.m8n8.x4.shared.b16 {%0,%1,%2,%3}, [%4];"
                        : "=r"(afl[mt][0]), "=r"(afl[mt][1]), "=r"(afl[mt][2]), "=r"(afl[mt][3]) : "r"(al_));
                }
            }
            uint32_t bfh[NT][2], bfl[NT][2];
#pragma unroll
            for (int jt = 0; jt < NT; jt += 2) {
                uint32_t bh_ = (uint32_t)__cvta_generic_to_shared(&sBh[(wn + jt*8 + b_row) * LDS + kc + b_kh]);
                uint32_t bl_ = (uint32_t)__cvta_generic_to_shared(&sBl[(wn + jt*8 + b_row) * LDS + kc + b_kh]);
                asm volatile("ldmatrix.sync.aligned.m8n8.x4.shared.b16 {%0,%1,%2,%3}, [%4];"
                    : "=r"(bfh[jt][0]), "=r"(bfh[jt][1]), "=r"(bfh[jt+1][0]), "=r"(bfh[jt+1][1]) : "r"(bh_));
                asm volatile("ldmatrix.sync.aligned.m8n8.x4.shared.b16 {%0,%1,%2,%3}, [%4];"
                    : "=r"(bfl[jt][0]), "=r"(bfl[jt][1]), "=r"(bfl[jt+1][0]), "=r"(bfl[jt+1][1]) : "r"(bl_));
            }
#pragma unroll
            for (int mt = 0; mt < MT; mt++)
#pragma unroll
                for (int jt = 0; jt < NT; jt++) {
                    float* d = acc[mt][jt];
#define MMA_T(A0,A1,A2,A3,B0,B1)                                                  \
    if (F16)                                                                      \
        asm volatile("mma.sync.aligned.m16n8k16.row.col.f32.f16.f16.f32 "        \
            "{%0,%1,%2,%3}, {%4,%5,%6,%7}, {%8,%9}, {%0,%1,%2,%3};"              \
            : "+f"(d[0]), "+f"(d[1]), "+f"(d[2]), "+f"(d[3])                     \
            : "r"(A0), "r"(A1), "r"(A2), "r"(A3), "r"(B0), "r"(B1));             \
    else                                                                          \
        asm volatile("mma.sync.aligned.m16n8k16.row.col.f32.bf16.bf16.f32 "      \
            "{%0,%1,%2,%3}, {%4,%5,%6,%7}, {%8,%9}, {%0,%1,%2,%3};"              \
            : "+f"(d[0]), "+f"(d[1]), "+f"(d[2]), "+f"(d[3])                     \
            : "r"(A0), "r"(A1), "r"(A2), "r"(A3), "r"(B0), "r"(B1))
                    MMA_T(afh[mt][0], afh[mt][1], afh[mt][2], afh[mt][3], bfh[jt][0], bfh[jt][1]);
                    MMA_T(afh[mt][0], afh[mt][1], afh[mt][2], afh[mt][3], bfl[jt][0], bfl[jt][1]);
                    if (TERMS == 3)
                        MMA_T(afl[mt][0], afl[mt][1], afl[mt][2], afl[mt][3], bfh[jt][0], bfh[jt][1]);
                }
        }
        __syncthreads();
        cur ^= 1;
    }

    const int cr = lane >> 2, cc = (lane & 3) << 1;
    if (OMODE == 0) {
        float* Cb = C + blockIdx.z * c_bs;
        const float* Rb = res ? res + blockIdx.z * r_sb : nullptr;
#pragma unroll
        for (int mt = 0; mt < MT; mt++)
#pragma unroll
            for (int jt = 0; jt < NT; jt++) {
#pragma unroll
                for (int half = 0; half < 2; half++) {
                    long long row = m0 + wm + mt*16 + cr + half*8;
                    long long col = n0 + wn + jt*8 + cc;
                    float v0 = acc[mt][jt][half*2 + 0];
                    float v1 = acc[mt][jt][half*2 + 1];
                    if (BMODE == 1) { float bv = bias[row]; v0 += bv; v1 += bv; }
                    else if (BMODE == 2) { v0 += bias[col]; v1 += bias[col + 1]; }
                    if (Rb) {
                        const float2 rv = *(const float2*)&Rb[row * ldc + col];
                        v0 += rv.x; v1 += rv.y;
                    }
                    *(float2*)&Cb[row * ldc + col] = make_float2(v0, v1);
                }
            }
    } else if (OMODE == 1) {
        bf16* DhB = Dh + blockIdx.z * c_bs;
        bf16* DlB = Dl + blockIdx.z * c_bs;
#pragma unroll
        for (int mt = 0; mt < MT; mt++)
#pragma unroll
            for (int jt = 0; jt < NT; jt++) {
#pragma unroll
                for (int half = 0; half < 2; half++) {
                    long long row = m0 + wm + mt*16 + cr + half*8;
                    long long col = n0 + wn + jt*8 + cc;
                    float v0 = acc[mt][jt][half*2 + 0];
                    float v1 = acc[mt][jt][half*2 + 1];
                    if (BMODE == 1) { float bv = bias[row]; v0 += bv; v1 += bv; }
                    else if (BMODE == 2) { v0 += bias[col]; v1 += bias[col + 1]; }
                    bf16 h0 = __float2bfloat16_rn(v0);
                    bf16 h1 = __float2bfloat16_rn(v1);
                    __nv_bfloat162 hp; hp.x = h0; hp.y = h1;
                    __nv_bfloat162 lp;
                    lp.x = __float2bfloat16_rn(v0 - __bfloat162float(h0));
                    lp.y = __float2bfloat16_rn(v1 - __bfloat162float(h1));
                    *(__nv_bfloat162*)&DhB[row * ldc + col] = hp;
                    *(__nv_bfloat162*)&DlB[row * ldc + col] = lp;
                }
            }
    } else {
        __half* DhB = (__half*)(Dh + blockIdx.z * c_bs);
        __half* DlB = (__half*)(Dl + blockIdx.z * c_bs);
#pragma unroll
        for (int mt = 0; mt < MT; mt++)
#pragma unroll
            for (int jt = 0; jt < NT; jt++) {
#pragma unroll
                for (int half = 0; half < 2; half++) {
                    long long row = m0 + wm + mt*16 + cr + half*8;
                    long long col = n0 + wn + jt*8 + cc;
                    float v0 = acc[mt][jt][half*2 + 0];
                    float v1 = acc[mt][jt][half*2 + 1];
                    if (BMODE == 1) { float bv = bias[row]; v0 += bv; v1 += bv; }
                    else if (BMODE == 2) { v0 += bias[col]; v1 += bias[col + 1]; }
                    __half h0 = __float2half_rn(v0);
                    __half h1 = __float2half_rn(v1);
                    __half2 hp; hp.x = h0; hp.y = h1;
                    __half2 lp;
                    lp.x = __float2half_rn(v0 - __half2float(h0));
                    lp.y = __float2half_rn(v1 - __half2float(h1));
                    *(__half2*)&DhB[row * ldc + col] = hp;
                    *(__half2*)&DlB[row * ldc + col] = lp;
                }
            }
    }
#undef MMA_T
}

// ----------------------------------------------------------------------------
// Fused flash attention: S = QK^T (3-term bf16), online softmax, O = P V
// (2-term fp16). One CTA = 128 query rows; 8 warps x 16 rows, full 128-j span.
// smem: Q tile resident + single K tile + single V tile, LDT=136.
// ----------------------------------------------------------------------------
#define LDT 136
__global__ void __launch_bounds__(256)
flash_attn(const bf16* __restrict__ qh, const bf16* __restrict__ ql,
           const bf16* __restrict__ kh, const bf16* __restrict__ kl,
           const bf16* __restrict__ vh, const bf16* __restrict__ vl,
           bf16* __restrict__ oh, bf16* __restrict__ ol)
{
    extern __shared__ bf16 sm[];
    bf16* qt = sm;                  // [256][LDT]  rows 0-127 = h, 128-255 = l
    bf16* kt = sm + 256 * LDT;      // [256][LDT]
    bf16* vt = sm + 512 * LDT;      // [256][LDT]

    const int tid  = threadIdx.x;
    const int warp = tid >> 5;
    const int lane = tid & 31;
    const long long b  = blockIdx.y;
    const int i0 = blockIdx.x * 128;
    const long long qsb = (long long)PN * PCI;
    const long long vsb = (long long)PCI * PN;

    const bf16* Qh = qh + b * qsb + (long long)i0 * PCI;
    const bf16* Ql = ql + b * qsb + (long long)i0 * PCI;
    const bf16* Kh = kh + b * qsb;
    const bf16* Kl = kl + b * qsb;
    const bf16* Vh = vh + b * vsb;
    const bf16* Vl = vl + b * vsb;

    auto ldK = [&](int j0) {
#pragma unroll
        for (int p = 0; p < 16; p++) {
            int qid = tid + p * 256, r = qid >> 4, qd = (qid & 15) << 3;
            const bf16* src = (r < 128) ? (Kh + (long long)(j0 + r) * PCI + qd)
                                        : (Kl + (long long)(j0 + r - 128) * PCI + qd);
            uint32_t dst = (uint32_t)__cvta_generic_to_shared(&kt[r * LDT + qd]);
            asm volatile("cp.async.cg.shared.global [%0], [%1], 16;" :: "r"(dst), "l"(src));
        }
    };
    auto ldV = [&](int j0) {
#pragma unroll
        for (int p = 0; p < 16; p++) {
            int qid = tid + p * 256, r = qid >> 4, qd = (qid & 15) << 3;
            const bf16* src = (r < 128) ? (Vh + (long long)r * PN + j0 + qd)
                                        : (Vl + (long long)(r - 128) * PN + j0 + qd);
            uint32_t dst = (uint32_t)__cvta_generic_to_shared(&vt[r * LDT + qd]);
            asm volatile("cp.async.cg.shared.global [%0], [%1], 16;" :: "r"(dst), "l"(src));
        }
    };

    // prologue: Q + K0 in one group
#pragma unroll
    for (int p = 0; p < 16; p++) {
        int qid = tid + p * 256, r = qid >> 4, qd = (qid & 15) << 3;
        const bf16* src = (r < 128) ? (Qh + (long long)r * PCI + qd)
                                    : (Ql + (long long)(r - 128) * PCI + qd);
        uint32_t dst = (uint32_t)__cvta_generic_to_shared(&qt[r * LDT + qd]);
        asm volatile("cp.async.cg.shared.global [%0], [%1], 16;" :: "r"(dst), "l"(src));
    }
    ldK(0);
    asm volatile("cp.async.commit_group;");

    float acc_o[16][4];
#pragma unroll
    for (int nt = 0; nt < 16; nt++)
#pragma unroll
        for (int r = 0; r < 4; r++) acc_o[nt][r] = 0.0f;
    float m0 = -1e30f, m1 = -1e30f, l0 = 0.0f, l1 = 0.0f;

    const int a_row = lane & 15, a_kh = (lane >> 4) << 3;
    const int b_row = (lane & 7) + ((lane >> 4) << 3), b_kh = lane & 8;
    const int wm = warp * 16;

    for (int jb = 0; jb < PN / 128; jb++) {
        asm volatile("cp.async.wait_group 0;");   // K_jb (+Q first iter)
        __syncthreads();                          // V buf free (prev PV done)
        ldV(jb * 128);
        asm volatile("cp.async.commit_group;");

        // ---- S = Q K^T (bf16 3-term) ----
        float s[16][4];
#pragma unroll
        for (int jt = 0; jt < 16; jt++)
#pragma unroll
            for (int r = 0; r < 4; r++) s[jt][r] = 0.0f;

#pragma unroll
        for (int ks = 0; ks < 8; ks++) {
            const int kc = ks * 16;
            uint32_t aqh[4], aql[4];
            uint32_t ah_ = (uint32_t)__cvta_generic_to_shared(&qt[(wm + a_row) * LDT + kc + a_kh]);
            uint32_t al_ = (uint32_t)__cvta_generic_to_shared(&qt[(128 + wm + a_row) * LDT + kc + a_kh]);
            asm volatile("ldmatrix.sync.aligned.m8n8.x4.shared.b16 {%0,%1,%2,%3}, [%4];"
                : "=r"(aqh[0]), "=r"(aqh[1]), "=r"(aqh[2]), "=r"(aqh[3]) : "r"(ah_));
            asm volatile("ldmatrix.sync.aligned.m8n8.x4.shared.b16 {%0,%1,%2,%3}, [%4];"
                : "=r"(aql[0]), "=r"(aql[1]), "=r"(aql[2]), "=r"(aql[3]) : "r"(al_));
#pragma unroll
            for (int jt = 0; jt < 16; jt += 2) {
                uint32_t bh0, bh1, bh2, bh3, bl0, bl1, bl2, bl3;
                uint32_t kh_ = (uint32_t)__cvta_generic_to_shared(&kt[(jt*8 + b_row) * LDT + kc + b_kh]);
                uint32_t kl_ = (uint32_t)__cvta_generic_to_shared(&kt[(128 + jt*8 + b_row) * LDT + kc + b_kh]);
                asm volatile("ldmatrix.sync.aligned.m8n8.x4.shared.b16 {%0,%1,%2,%3}, [%4];"
                    : "=r"(bh0), "=r"(bh1), "=r"(bh2), "=r"(bh3) : "r"(kh_));
                asm volatile("ldmatrix.sync.aligned.m8n8.x4.shared.b16 {%0,%1,%2,%3}, [%4];"
                    : "=r"(bl0), "=r"(bl1), "=r"(bl2), "=r"(bl3) : "r"(kl_));
#define MMA_BF(D,A0,A1,A2,A3,B0,B1)                                               \
    asm volatile("mma.sync.aligned.m16n8k16.row.col.f32.bf16.bf16.f32 "          \
        "{%0,%1,%2,%3}, {%4,%5,%6,%7}, {%8,%9}, {%0,%1,%2,%3};"                  \
        : "+f"(D[0]), "+f"(D[1]), "+f"(D[2]), "+f"(D[3])                         \
        : "r"(A0), "r"(A1), "r"(A2), "r"(A3), "r"(B0), "r"(B1))
                MMA_BF(s[jt],   aqh[0], aqh[1], aqh[2], aqh[3], bh0, bh1);
                MMA_BF(s[jt],   aqh[0], aqh[1], aqh[2], aqh[3], bl0, bl1);
                MMA_BF(s[jt],   aql[0], aql[1], aql[2], aql[3], bh0, bh1);
                MMA_BF(s[jt+1], aqh[0], aqh[1], aqh[2], aqh[3], bh2, bh3);
                MMA_BF(s[jt+1], aqh[0], aqh[1], aqh[2], aqh[3], bl2, bl3);
                MMA_BF(s[jt+1], aql[0], aql[1], aql[2], aql[3], bh2, bh3);
#undef MMA_BF
            }
        }

        // ---- online softmax (warp covers full j span -> warp-local) ----
        float rmax0 = -1e30f, rmax1 = -1e30f;
#pragma unroll
        for (int jt = 0; jt < 16; jt++) {
            rmax0 = fmaxf(rmax0, fmaxf(s[jt][0], s[jt][1]));
            rmax1 = fmaxf(rmax1, fmaxf(s[jt][2], s[jt][3]));
        }
        rmax0 = fmaxf(rmax0, __shfl_xor_sync(0xffffffffu, rmax0, 1));
        rmax0 = fmaxf(rmax0, __shfl_xor_sync(0xffffffffu, rmax0, 2));
        rmax1 = fmaxf(rmax1, __shfl_xor_sync(0xffffffffu, rmax1, 1));
        rmax1 = fmaxf(rmax1, __shfl_xor_sync(0xffffffffu, rmax1, 2));
        const float nm0 = fmaxf(m0, rmax0), nm1 = fmaxf(m1, rmax1);
        const float al0 = __expf(m0 - nm0), al1 = __expf(m1 - nm1);
        float sum0 = 0.0f, sum1 = 0.0f;
#pragma unroll
        for (int jt = 0; jt < 16; jt++) {
            s[jt][0] = __expf(s[jt][0] - nm0);
            s[jt][1] = __expf(s[jt][1] - nm0);
            s[jt][2] = __expf(s[jt][2] - nm1);
            s[jt][3] = __expf(s[jt][3] - nm1);
            sum0 += s[jt][0] + s[jt][1];
            sum1 += s[jt][2] + s[jt][3];
        }
        sum0 += __shfl_xor_sync(0xffffffffu, sum0, 1);
        sum0 += __shfl_xor_sync(0xffffffffu, sum0, 2);
        sum1 += __shfl_xor_sync(0xffffffffu, sum1, 1);
        sum1 += __shfl_xor_sync(0xffffffffu, sum1, 2);
        l0 = l0 * al0 + sum0;
        l1 = l1 * al1 + sum1;
        m0 = nm0; m1 = nm1;
#pragma unroll
        for (int nt = 0; nt < 16; nt++) {
            acc_o[nt][0] *= al0; acc_o[nt][1] *= al0;
            acc_o[nt][2] *= al1; acc_o[nt][3] *= al1;
        }

        asm volatile("cp.async.wait_group 0;");   // V_jb
        __syncthreads();                          // K buf free (S done by all)
        if (jb + 1 < PN / 128) {
            ldK((jb + 1) * 128);
            asm volatile("cp.async.commit_group;");
        }

        // ---- O += P V (fp16 2-term); A frags packed from P regs ----
#pragma unroll
        for (int kc = 0; kc < 8; kc++) {
            __half2 t0, t1, t2, t3;
            t0.x = __float2half_rn(s[2*kc][0]);   t0.y = __float2half_rn(s[2*kc][1]);
            t1.x = __float2half_rn(s[2*kc][2]);   t1.y = __float2half_rn(s[2*kc][3]);
            t2.x = __float2half_rn(s[2*kc+1][0]); t2.y = __float2half_rn(s[2*kc+1][1]);
            t3.x = __float2half_rn(s[2*kc+1][2]); t3.y = __float2half_rn(s[2*kc+1][3]);
            uint32_t a0 = *(uint32_t*)&t0, a1 = *(uint32_t*)&t1;
            uint32_t a2 = *(uint32_t*)&t2, a3 = *(uint32_t*)&t3;
#pragma unroll
            for (int nt = 0; nt < 16; nt += 2) {
                uint32_t bh0, bh1, bh2, bh3, bl0, bl1, bl2, bl3;
                uint32_t vh_ = (uint32_t)__cvta_generic_to_shared(&vt[(nt*8 + b_row) * LDT + kc*16 + b_kh]);
                uint32_t vl_ = (uint32_t)__cvta_generic_to_shared(&vt[(128 + nt*8 + b_row) * LDT + kc*16 + b_kh]);
                asm volatile("ldmatrix.sync.aligned.m8n8.x4.shared.b16 {%0,%1,%2,%3}, [%4];"
                    : "=r"(bh0), "=r"(bh1), "=r"(bh2), "=r"(bh3) : "r"(vh_));
                asm volatile("ldmatrix.sync.aligned.m8n8.x4.shared.b16 {%0,%1,%2,%3}, [%4];"
                    : "=r"(bl0), "=r"(bl1), "=r"(bl2), "=r"(bl3) : "r"(vl_));
#define MMA_F16(D,B0,B1)                                                          \
    asm volatile("mma.sync.aligned.m16n8k16.row.col.f32.f16.f16.f32 "            \
        "{%0,%1,%2,%3}, {%4,%5,%6,%7}, {%8,%9}, {%0,%1,%2,%3};"                  \
        : "+f"(D[0]), "+f"(D[1]), "+f"(D[2]), "+f"(D[3])                         \
        : "r"(a0), "r"(a1), "r"(a2), "r"(a3), "r"(B0), "r"(B1))
                MMA_F16(acc_o[nt],   bh0, bh1);
                MMA_F16(acc_o[nt],   bl0, bl1);
                MMA_F16(acc_o[nt+1], bh2, bh3);
                MMA_F16(acc_o[nt+1], bl2, bl3);
#undef MMA_F16
            }
        }
    }

    // ---- epilogue: normalize, bf16 h/l out ----
    const int cr = lane >> 2, cc = (lane & 3) << 1;
    const float inv0 = 1.0f / l0, inv1 = 1.0f / l1;
    bf16* Oh = oh + b * qsb;
    bf16* Ol = ol + b * qsb;
    const long long r0 = i0 + wm + cr, r1 = r0 + 8;
#pragma unroll
    for (int nt = 0; nt < 16; nt++) {
        const long long col = nt*8 + cc;
        float v0 = acc_o[nt][0] * inv0, v1 = acc_o[nt][1] * inv0;
        float v2 = acc_o[nt][2] * inv1, v3 = acc_o[nt][3] * inv1;
        bf16 h0 = __float2bfloat16_rn(v0), h1 = __float2bfloat16_rn(v1);
        bf16 h2 = __float2bfloat16_rn(v2), h3 = __float2bfloat16_rn(v3);
        __nv_bfloat162 hp0; hp0.x = h0; hp0.y = h1;
        __nv_bfloat162 hp1; hp1.x = h2; hp1.y = h3;
        __nv_bfloat162 lp0, lp1;
        lp0.x = __float2bfloat16_rn(v0 - __bfloat162float(h0));
        lp0.y = __float2bfloat16_rn(v1 - __bfloat162float(h1));
        lp1.x = __float2bfloat16_rn(v2 - __bfloat162float(h2));
        lp1.y = __float2bfloat16_rn(v3 - __bfloat162float(h3));
        *(__nv_bfloat162*)&Oh[r0 * PCI + col] = hp0;
        *(__nv_bfloat162*)&Ol[r0 * PCI + col] = lp0;
        *(__nv_bfloat162*)&Oh[r1 * PCI + col] = hp1;
        *(__nv_bfloat162*)&Ol[r1 * PCI + col] = lp1;
    }
}

// ----------------------------------------------------------------------------
// Transpose + hi/lo split: src fp32 [b][R][N] -> dh/dl bf16 [b][N][R]
// ----------------------------------------------------------------------------
__global__ void __launch_bounds__(256)
tsplit(const float* __restrict__ src, bf16* __restrict__ dh, bf16* __restrict__ dl, int R)
{
    __shared__ float t[32][33];
    const int tx = threadIdx.x, ty = threadIdx.y;
    const long long b = blockIdx.z;
    const int n0 = blockIdx.x * 32, r0 = blockIdx.y * 32;
    const float* S = src + b * (long long)R * PN;
#pragma unroll
    for (int i = 0; i < 4; i++)
        t[ty + i*8][tx] = S[(long long)(r0 + ty + i*8) * PN + n0 + tx];
    __syncthreads();
    bf16* DH = dh + b * (long long)R * PN;
    bf16* DL = dl + b * (long long)R * PN;
#pragma unroll
    for (int i = 0; i < 4; i++) {
        float v = t[tx][ty + i*8];
        bf16 h = __float2bfloat16_rn(v);
        long long off = (long long)(n0 + ty + i*8) * R + r0 + tx;
        DH[off] = h;
        DL[off] = __float2bfloat16_rn(v - __bfloat162float(h));
    }
}

// Elementwise hi/lo split (weights)
__global__ void __launch_bounds__(256)
esplit(const float* __restrict__ src, bf16* __restrict__ dh, bf16* __restrict__ dl, int n)
{
    int i = blockIdx.x * 256 + threadIdx.x;
    if (i < n) {
        float v = src[i];
        bf16 h = __float2bfloat16_rn(v);
        dh[i] = h;
        dl[i] = __float2bfloat16_rn(v - __bfloat162float(h));
    }
}

// ----------------------------------------------------------------------------
// Launch
// ----------------------------------------------------------------------------
extern "C" void kernel_launch(void* const* d_in, const int* in_sizes, int n_in,
                              void* d_out, int out_size)
{
    (void)in_sizes; (void)n_in; (void)out_size;
    const float* x  = (const float*)d_in[0];
    const float* wq = (const float*)d_in[1];
    const float* bq = (const float*)d_in[2];
    const float* wk = (const float*)d_in[3];
    const float* bk = (const float*)d_in[4];
    const float* wv = (const float*)d_in[5];
    const float* bv = (const float*)d_in[6];
    const float* wo = (const float*)d_in[7];
    const float* bo = (const float*)d_in[8];
    float* out = (float*)d_out;

    const int SM_P3 = 2 * (2*64  + 2*128) * 40 * 2;   // 61440
    const int SM_E  = 2 * (2*128 + 2*128) * 40 * 2;   // 81920
    const int SM_FA = 768 * LDT * 2;                  // 208896

    static bf16 *xth = nullptr, *xtl,*qh,*ql,*kh,*kl,*vh,*vl,*oh,*ol;
    static bf16 *wqh,*wql,*wkh,*wkl,*wvh,*wvl,*woh,*wol;
    if (!xth) {
        cudaGetSymbolAddress((void**)&xth, g_xth);
        cudaGetSymbolAddress((void**)&xtl, g_xtl);
        cudaGetSymbolAddress((void**)&qh,  g_qh);
        cudaGetSymbolAddress((void**)&ql,  g_ql);
        cudaGetSymbolAddress((void**)&kh,  g_kh);
        cudaGetSymbolAddress((void**)&kl,  g_kl);
        cudaGetSymbolAddress((void**)&vh,  g_vh);
        cudaGetSymbolAddress((void**)&vl,  g_vl);
        cudaGetSymbolAddress((void**)&oh,  g_oh);
        cudaGetSymbolAddress((void**)&ol,  g_ol);
        cudaGetSymbolAddress((void**)&wqh, g_wqh);
        cudaGetSymbolAddress((void**)&wql, g_wql);
        cudaGetSymbolAddress((void**)&wkh, g_wkh);
        cudaGetSymbolAddress((void**)&wkl, g_wkl);
        cudaGetSymbolAddress((void**)&wvh, g_wvh);
        cudaGetSymbolAddress((void**)&wvl, g_wvl);
        cudaGetSymbolAddress((void**)&woh, g_woh);
        cudaGetSymbolAddress((void**)&wol, g_wol);
        cudaFuncSetAttribute(mma_gemm3<64,128,32,32,1,2,3,false>,
                             cudaFuncAttributeMaxDynamicSharedMemorySize, SM_P3);
        cudaFuncSetAttribute(mma_gemm3<64,128,32,32,2,1,3,false>,
                             cudaFuncAttributeMaxDynamicSharedMemorySize, SM_P3);
        cudaFuncSetAttribute(mma_gemm3<128,128,32,64,0,1,3,false>,
                             cudaFuncAttributeMaxDynamicSharedMemorySize, SM_E);
        cudaFuncSetAttribute(flash_attn,
                             cudaFuncAttributeMaxDynamicSharedMemorySize, SM_FA);
    }

    const long long N = PN, C = PC, CI = PCI;
    const long long xsb = C * N;
    const long long tsb = N * C;
    const long long qsb = N * CI;
    const long long vsb = CI * N;
    dim3 blk(256);

    // 0) split x (transposed) + weights
    tsplit<<<dim3(PN/32, PC/32, PB), dim3(32,8)>>>(x, xth, xtl, PC);
    esplit<<<PCI*PC/256, blk>>>(wq, wqh, wql, PCI*PC);
    esplit<<<PCI*PC/256, blk>>>(wk, wkh, wkl, PCI*PC);
    esplit<<<PCI*PC/256, blk>>>(wv, wvh, wvl, PCI*PC);
    esplit<<<PC*PCI/256, blk>>>(wo, woh, wol, PC*PCI);

    // 1) q,k projections -> bf16 h/l [b][i][ci]
    mma_gemm3<64,128,32,32,1,2,3,false><<<dim3(1, PN/64, PB), blk, SM_P3>>>(
        xth, xtl, tsb, PC,  wqh, wql, 0, PC,
        nullptr, qh, ql, qsb, PCI,  bq, nullptr, 0, PC);
    mma_gemm3<64,128,32,32,1,2,3,false><<<dim3(1, PN/64, PB), blk, SM_P3>>>(
        xth, xtl, tsb, PC,  wkh, wkl, 0, PC,
        nullptr, kh, kl, qsb, PCI,  bk, nullptr, 0, PC);

    // 2) v projection -> fp16 h/l [b][ci][j]
    mma_gemm3<64,128,32,32,2,1,3,false><<<dim3(PN/128, PCI/64, PB), blk, SM_P3>>>(
        wvh, wvl, 0, PC,  xth, xtl, tsb, PC,
        nullptr, vh, vl, vsb, PN,  bv, nullptr, 0, PC);

    // 3) fused attention: energy + softmax + PV -> oh/ol bf16 h/l [b][i][ci]
    flash_attn<<<dim3(PN/128, PB), blk, SM_FA>>>(qh, ql, kh, kl, vh, vl, oh, ol);

    // 4) out = wo * O^T + bo + x -> fp32 d_out
    mma_gemm3<128,128,32,64,0,1,3,false><<<dim3(PN/128, PC/128, PB), blk, SM_E>>>(
        woh, wol, 0, PCI,  oh, ol, qsb, PCI,
        out, nullptr, nullptr, xsb, PN,  bo, x, xsb, PCI);
}

// round 17
// speedup vs baseline: 2.0047x; 1.1280x over previous
#include <cuda_runtime.h>
#include <cuda_bf16.h>
#include <cuda_fp16.h>
#include <cstdint>

// Problem constants: B=4, C=512, CI=128, H=W=64, N=4096
#define PB  4
#define PC  512
#define PCI 128
#define PN  4096

typedef __nv_bfloat16 bf16;

// ---------------- scratch (~75 MB of __device__ globals) --------------------
__device__ __align__(256) bf16  g_xth[(size_t)PB * PN * PC]; // x^T hi [b][n][c]
__device__ __align__(256) bf16  g_xtl[(size_t)PB * PN * PC];
__device__ __align__(256) bf16  g_qh[(size_t)PB * PN * PCI]; // [b][i][ci] bf16 h/l
__device__ __align__(256) bf16  g_ql[(size_t)PB * PN * PCI];
__device__ __align__(256) bf16  g_kh[(size_t)PB * PN * PCI];
__device__ __align__(256) bf16  g_kl[(size_t)PB * PN * PCI];
__device__ __align__(256) bf16  g_vh[(size_t)PB * PCI * PN]; // [b][ci][j] fp16 h/l bit patterns
__device__ __align__(256) bf16  g_vl[(size_t)PB * PCI * PN];
__device__ __align__(256) bf16  g_oh[(size_t)PB * PN * PCI]; // [b][i][ci] bf16 h/l
__device__ __align__(256) bf16  g_ol[(size_t)PB * PN * PCI];
__device__ __align__(256) bf16  g_wqh[PCI * PC], g_wql[PCI * PC];
__device__ __align__(256) bf16  g_wkh[PCI * PC], g_wkl[PCI * PC];
__device__ __align__(256) bf16  g_wvh[PCI * PC], g_wvl[PCI * PC];
__device__ __align__(256) bf16  g_woh[PC * PCI], g_wol[PC * PCI];

// ----------------------------------------------------------------------------
// Tensor-core GEMM, hi/lo split, cp.async double-buffered (projections/out-proj)
// OMODE: 0 = fp32 out (+res), 1 = bf16 h/l out, 2 = fp16 h/l out
// BMODE: 0 = none, 1 = bias[m], 2 = bias[n]
// TERMS: 3 = ah*bh + ah*bl + al*bh ; 2 = ah*bh + ah*bl
// ----------------------------------------------------------------------------
template<int BM, int BN, int WM, int WN, int OMODE, int BMODE, int TERMS, bool F16>
__global__ void __launch_bounds__(256)
mma_gemm3(const bf16* __restrict__ Ah, const bf16* __restrict__ Al,
          long long a_bs, int lda,
          const bf16* __restrict__ Bh, const bf16* __restrict__ Bl,
          long long b_bs, int ldb,
          float* __restrict__ C, bf16* __restrict__ Dh, bf16* __restrict__ Dl,
          long long c_bs, int ldc,
          const float* __restrict__ bias,
          const float* __restrict__ res, long long r_sb,
          int K)
{
    constexpr int BK  = 32;
    constexpr int LDS = 40;
    constexpr int WARPS_M = BM / WM;
    constexpr int MT = WM / 16;
    constexpr int NT = WN / 8;
    constexpr int AROWS = (TERMS == 3) ? 2 * BM : BM;
    constexpr int SROWS = AROWS + 2 * BN;
    constexpr int PASSES = (SROWS + 63) / 64;
    constexpr int STG = SROWS * LDS;

    extern __shared__ bf16 sm[];

    const int tid  = threadIdx.x;
    const int warp = tid >> 5;
    const int lane = tid & 31;
    const int wm = (warp % WARPS_M) * WM;
    const int wn = (warp / WARPS_M) * WN;

    const long long m0 = (long long)blockIdx.y * BM;
    const long long n0 = (long long)blockIdx.x * BN;
    const bf16* Abh = Ah + blockIdx.z * a_bs + m0 * lda;
    const bf16* Abl = Al + blockIdx.z * a_bs + m0 * lda;
    const bf16* Bbh = Bh + blockIdx.z * b_bs + n0 * ldb;
    const bf16* Bbl = Bl + blockIdx.z * b_bs + n0 * ldb;

    float acc[MT][NT][4];
#pragma unroll
    for (int i = 0; i < MT; i++)
#pragma unroll
        for (int j = 0; j < NT; j++)
#pragma unroll
            for (int r = 0; r < 4; r++) acc[i][j][r] = 0.0f;

    const int a_row = lane & 15, a_kh = (lane >> 4) << 3;
    const int b_row = (lane & 7) + ((lane >> 4) << 3), b_kh = lane & 8;

    const int lrow = tid >> 2;
    const int lq8  = (tid & 3) << 3;

    auto issue = [&](int stage, int kt) {
#pragma unroll
        for (int p = 0; p < PASSES; p++) {
            int r = lrow + p * 64;
            if (r < SROWS) {
                const bf16* src;
                if (r < BM)                 src = Abh + (long long)r * lda + kt + lq8;
                else if (r < AROWS)         src = Abl + (long long)(r - BM) * lda + kt + lq8;
                else if (r < AROWS + BN)    src = Bbh + (long long)(r - AROWS) * ldb + kt + lq8;
                else                        src = Bbl + (long long)(r - AROWS - BN) * ldb + kt + lq8;
                uint32_t dst = (uint32_t)__cvta_generic_to_shared(&sm[(size_t)stage * STG + r * LDS + lq8]);
                asm volatile("cp.async.cg.shared.global [%0], [%1], 16;" :: "r"(dst), "l"(src));
            }
        }
        asm volatile("cp.async.commit_group;");
    };

    issue(0, 0);
    int cur = 0;

    for (int kt = 0; kt < K; kt += BK) {
        const bool has_next = (kt + BK < K);
        if (has_next) {
            issue(cur ^ 1, kt + BK);
            asm volatile("cp.async.wait_group 1;");
        } else {
            asm volatile("cp.async.wait_group 0;");
        }
        __syncthreads();

        bf16* sAh = sm + (size_t)cur * STG;
        bf16* sAl = sAh + BM * LDS;
        bf16* sBh = sAh + AROWS * LDS;
        bf16* sBl = sBh + BN * LDS;

#pragma unroll
        for (int ks = 0; ks < 2; ks++) {
            const int kc = ks * 16;
            uint32_t afh[MT][4], afl[MT][4];
#pragma unroll
            for (int mt = 0; mt < MT; mt++) {
                uint32_t ah_ = (uint32_t)__cvta_generic_to_shared(&sAh[(wm + mt*16 + a_row) * LDS + kc + a_kh]);
                asm volatile("ldmatrix.sync.aligned.m8n8.x4.shared.b16 {%0,%1,%2,%3}, [%4];"
                    : "=r"(afh[mt][0]), "=r"(afh[mt][1]), "=r"(afh[mt][2]), "=r"(afh[mt][3]) : "r"(ah_));
                if (TERMS == 3) {
                    uint32_t al_ = (uint32_t)__cvta_generic_to_shared(&sAl[(wm + mt*16 + a_row) * LDS + kc + a_kh]);
                    asm volatile("ldmatrix.sync.aligned.m8n8.x4.shared.b16 {%0,%1,%2,%3}, [%4];"
                        : "=r"(afl[mt][0]), "=r"(afl[mt][1]), "=r"(afl[mt][2]), "=r"(afl[mt][3]) : "r"(al_));
                }
            }
            uint32_t bfh[NT][2], bfl[NT][2];
#pragma unroll
            for (int jt = 0; jt < NT; jt += 2) {
                uint32_t bh_ = (uint32_t)__cvta_generic_to_shared(&sBh[(wn + jt*8 + b_row) * LDS + kc + b_kh]);
                uint32_t bl_ = (uint32_t)__cvta_generic_to_shared(&sBl[(wn + jt*8 + b_row) * LDS + kc + b_kh]);
                asm volatile("ldmatrix.sync.aligned.m8n8.x4.shared.b16 {%0,%1,%2,%3}, [%4];"
                    : "=r"(bfh[jt][0]), "=r"(bfh[jt][1]), "=r"(bfh[jt+1][0]), "=r"(bfh[jt+1][1]) : "r"(bh_));
                asm volatile("ldmatrix.sync.aligned.m8n8.x4.shared.b16 {%0,%1,%2,%3}, [%4];"
                    : "=r"(bfl[jt][0]), "=r"(bfl[jt][1]), "=r"(bfl[jt+1][0]), "=r"(bfl[jt+1][1]) : "r"(bl_));
            }
#pragma unroll
            for (int mt = 0; mt < MT; mt++)
#pragma unroll
                for (int jt = 0; jt < NT; jt++) {
                    float* d = acc[mt][jt];
#define MMA_T(A0,A1,A2,A3,B0,B1)                                                  \
    if (F16)                                                                      \
        asm volatile("mma.sync.aligned.m16n8k16.row.col.f32.f16.f16.f32 "        \
            "{%0,%1,%2,%3}, {%4,%5,%6,%7}, {%8,%9}, {%0,%1,%2,%3};"              \
            : "+f"(d[0]), "+f"(d[1]), "+f"(d[2]), "+f"(d[3])                     \
            : "r"(A0), "r"(A1), "r"(A2), "r"(A3), "r"(B0), "r"(B1));             \
    else                                                                          \
        asm volatile("mma.sync.aligned.m16n8k16.row.col.f32.bf16.bf16.f32 "      \
            "{%0,%1,%2,%3}, {%4,%5,%6,%7}, {%8,%9}, {%0,%1,%2,%3};"              \
            : "+f"(d[0]), "+f"(d[1]), "+f"(d[2]), "+f"(d[3])                     \
            : "r"(A0), "r"(A1), "r"(A2), "r"(A3), "r"(B0), "r"(B1))
                    MMA_T(afh[mt][0], afh[mt][1], afh[mt][2], afh[mt][3], bfh[jt][0], bfh[jt][1]);
                    MMA_T(afh[mt][0], afh[mt][1], afh[mt][2], afh[mt][3], bfl[jt][0], bfl[jt][1]);
                    if (TERMS == 3)
                        MMA_T(afl[mt][0], afl[mt][1], afl[mt][2], afl[mt][3], bfh[jt][0], bfh[jt][1]);
                }
        }
        __syncthreads();
        cur ^= 1;
    }

    const int cr = lane >> 2, cc = (lane & 3) << 1;
    if (OMODE == 0) {
        float* Cb = C + blockIdx.z * c_bs;
        const float* Rb = res ? res + blockIdx.z * r_sb : nullptr;
#pragma unroll
        for (int mt = 0; mt < MT; mt++)
#pragma unroll
            for (int jt = 0; jt < NT; jt++) {
#pragma unroll
                for (int half = 0; half < 2; half++) {
                    long long row = m0 + wm + mt*16 + cr + half*8;
                    long long col = n0 + wn + jt*8 + cc;
                    float v0 = acc[mt][jt][half*2 + 0];
                    float v1 = acc[mt][jt][half*2 + 1];
                    if (BMODE == 1) { float bv = bias[row]; v0 += bv; v1 += bv; }
                    else if (BMODE == 2) { v0 += bias[col]; v1 += bias[col + 1]; }
                    if (Rb) {
                        const float2 rv = *(const float2*)&Rb[row * ldc + col];
                        v0 += rv.x; v1 += rv.y;
                    }
                    *(float2*)&Cb[row * ldc + col] = make_float2(v0, v1);
                }
            }
    } else if (OMODE == 1) {
        bf16* DhB = Dh + blockIdx.z * c_bs;
        bf16* DlB = Dl + blockIdx.z * c_bs;
#pragma unroll
        for (int mt = 0; mt < MT; mt++)
#pragma unroll
            for (int jt = 0; jt < NT; jt++) {
#pragma unroll
                for (int half = 0; half < 2; half++) {
                    long long row = m0 + wm + mt*16 + cr + half*8;
                    long long col = n0 + wn + jt*8 + cc;
                    float v0 = acc[mt][jt][half*2 + 0];
                    float v1 = acc[mt][jt][half*2 + 1];
                    if (BMODE == 1) { float bv = bias[row]; v0 += bv; v1 += bv; }
                    else if (BMODE == 2) { v0 += bias[col]; v1 += bias[col + 1]; }
                    bf16 h0 = __float2bfloat16_rn(v0);
                    bf16 h1 = __float2bfloat16_rn(v1);
                    __nv_bfloat162 hp; hp.x = h0; hp.y = h1;
                    __nv_bfloat162 lp;
                    lp.x = __float2bfloat16_rn(v0 - __bfloat162float(h0));
                    lp.y = __float2bfloat16_rn(v1 - __bfloat162float(h1));
                    *(__nv_bfloat162*)&DhB[row * ldc + col] = hp;
                    *(__nv_bfloat162*)&DlB[row * ldc + col] = lp;
                }
            }
    } else {
        __half* DhB = (__half*)(Dh + blockIdx.z * c_bs);
        __half* DlB = (__half*)(Dl + blockIdx.z * c_bs);
#pragma unroll
        for (int mt = 0; mt < MT; mt++)
#pragma unroll
            for (int jt = 0; jt < NT; jt++) {
#pragma unroll
                for (int half = 0; half < 2; half++) {
                    long long row = m0 + wm + mt*16 + cr + half*8;
                    long long col = n0 + wn + jt*8 + cc;
                    float v0 = acc[mt][jt][half*2 + 0];
                    float v1 = acc[mt][jt][half*2 + 1];
                    if (BMODE == 1) { float bv = bias[row]; v0 += bv; v1 += bv; }
                    else if (BMODE == 2) { v0 += bias[col]; v1 += bias[col + 1]; }
                    __half h0 = __float2half_rn(v0);
                    __half h1 = __float2half_rn(v1);
                    __half2 hp; hp.x = h0; hp.y = h1;
                    __half2 lp;
                    lp.x = __float2half_rn(v0 - __half2float(h0));
                    lp.y = __float2half_rn(v1 - __half2float(h1));
                    *(__half2*)&DhB[row * ldc + col] = hp;
                    *(__half2*)&DlB[row * ldc + col] = lp;
                }
            }
    }
#undef MMA_T
}

// ----------------------------------------------------------------------------
// Fused flash attention: S = QK^T (3-term bf16), online softmax, O = P Vh
// (1-term fp16). One CTA = 128 query rows; 8 warps x 16 rows, full 128-j span.
// smem: Q (256 rows h+l) + K (256 rows h+l) + V (128 rows, h only), LDT=136.
// ----------------------------------------------------------------------------
#define LDT 136
__global__ void __launch_bounds__(256)
flash_attn(const bf16* __restrict__ qh, const bf16* __restrict__ ql,
           const bf16* __restrict__ kh, const bf16* __restrict__ kl,
           const bf16* __restrict__ vh,
           bf16* __restrict__ oh, bf16* __restrict__ ol)
{
    extern __shared__ bf16 sm[];
    bf16* qt = sm;                  // [256][LDT]  rows 0-127 = h, 128-255 = l
    bf16* kt = sm + 256 * LDT;      // [256][LDT]
    bf16* vt = sm + 512 * LDT;      // [128][LDT]  (h only)

    const int tid  = threadIdx.x;
    const int warp = tid >> 5;
    const int lane = tid & 31;
    const long long b  = blockIdx.y;
    const int i0 = blockIdx.x * 128;
    const long long qsb = (long long)PN * PCI;
    const long long vsb = (long long)PCI * PN;

    const bf16* Qh = qh + b * qsb + (long long)i0 * PCI;
    const bf16* Ql = ql + b * qsb + (long long)i0 * PCI;
    const bf16* Kh = kh + b * qsb;
    const bf16* Kl = kl + b * qsb;
    const bf16* Vh = vh + b * vsb;

    auto ldK = [&](int j0) {
#pragma unroll
        for (int p = 0; p < 16; p++) {
            int qid = tid + p * 256, r = qid >> 4, qd = (qid & 15) << 3;
            const bf16* src = (r < 128) ? (Kh + (long long)(j0 + r) * PCI + qd)
                                        : (Kl + (long long)(j0 + r - 128) * PCI + qd);
            uint32_t dst = (uint32_t)__cvta_generic_to_shared(&kt[r * LDT + qd]);
            asm volatile("cp.async.cg.shared.global [%0], [%1], 16;" :: "r"(dst), "l"(src));
        }
    };
    auto ldV = [&](int j0) {
#pragma unroll
        for (int p = 0; p < 8; p++) {
            int qid = tid + p * 256, r = qid >> 4, qd = (qid & 15) << 3;
            const bf16* src = Vh + (long long)r * PN + j0 + qd;
            uint32_t dst = (uint32_t)__cvta_generic_to_shared(&vt[r * LDT + qd]);
            asm volatile("cp.async.cg.shared.global [%0], [%1], 16;" :: "r"(dst), "l"(src));
        }
    };

    // prologue: Q + K0 in one group
#pragma unroll
    for (int p = 0; p < 16; p++) {
        int qid = tid + p * 256, r = qid >> 4, qd = (qid & 15) << 3;
        const bf16* src = (r < 128) ? (Qh + (long long)r * PCI + qd)
                                    : (Ql + (long long)(r - 128) * PCI + qd);
        uint32_t dst = (uint32_t)__cvta_generic_to_shared(&qt[r * LDT + qd]);
        asm volatile("cp.async.cg.shared.global [%0], [%1], 16;" :: "r"(dst), "l"(src));
    }
    ldK(0);
    asm volatile("cp.async.commit_group;");

    float acc_o[16][4];
#pragma unroll
    for (int nt = 0; nt < 16; nt++)
#pragma unroll
        for (int r = 0; r < 4; r++) acc_o[nt][r] = 0.0f;
    float m0 = -1e30f, m1 = -1e30f, l0 = 0.0f, l1 = 0.0f;

    const int a_row = lane & 15, a_kh = (lane >> 4) << 3;
    const int b_row = (lane & 7) + ((lane >> 4) << 3), b_kh = lane & 8;
    const int wm = warp * 16;

    for (int jb = 0; jb < PN / 128; jb++) {
        asm volatile("cp.async.wait_group 0;");   // K_jb (+Q first iter)
        __syncthreads();                          // V buf free (prev PV done)
        ldV(jb * 128);
        asm volatile("cp.async.commit_group;");

        // ---- S = Q K^T (bf16 3-term) ----
        float s[16][4];
#pragma unroll
        for (int jt = 0; jt < 16; jt++)
#pragma unroll
            for (int r = 0; r < 4; r++) s[jt][r] = 0.0f;

#pragma unroll
        for (int ks = 0; ks < 8; ks++) {
            const int kc = ks * 16;
            uint32_t aqh[4], aql[4];
            uint32_t ah_ = (uint32_t)__cvta_generic_to_shared(&qt[(wm + a_row) * LDT + kc + a_kh]);
            uint32_t al_ = (uint32_t)__cvta_generic_to_shared(&qt[(128 + wm + a_row) * LDT + kc + a_kh]);
            asm volatile("ldmatrix.sync.aligned.m8n8.x4.shared.b16 {%0,%1,%2,%3}, [%4];"
                : "=r"(aqh[0]), "=r"(aqh[1]), "=r"(aqh[2]), "=r"(aqh[3]) : "r"(ah_));
            asm volatile("ldmatrix.sync.aligned.m8n8.x4.shared.b16 {%0,%1,%2,%3}, [%4];"
                : "=r"(aql[0]), "=r"(aql[1]), "=r"(aql[2]), "=r"(aql[3]) : "r"(al_));
#pragma unroll
            for (int jt = 0; jt < 16; jt += 2) {
                uint32_t bh0, bh1, bh2, bh3, bl0, bl1, bl2, bl3;
                uint32_t kh_ = (uint32_t)__cvta_generic_to_shared(&kt[(jt*8 + b_row) * LDT + kc + b_kh]);
                uint32_t kl_ = (uint32_t)__cvta_generic_to_shared(&kt[(128 + jt*8 + b_row) * LDT + kc + b_kh]);
                asm volatile("ldmatrix.sync.aligned.m8n8.x4.shared.b16 {%0,%1,%2,%3}, [%4];"
                    : "=r"(bh0), "=r"(bh1), "=r"(bh2), "=r"(bh3) : "r"(kh_));
                asm volatile("ldmatrix.sync.aligned.m8n8.x4.shared.b16 {%0,%1,%2,%3}, [%4];"
                    : "=r"(bl0), "=r"(bl1), "=r"(bl2), "=r"(bl3) : "r"(kl_));
#define MMA_BF(D,A0,A1,A2,A3,B0,B1)                                               \
    asm volatile("mma.sync.aligned.m16n8k16.row.col.f32.bf16.bf16.f32 "          \
        "{%0,%1,%2,%3}, {%4,%5,%6,%7}, {%8,%9}, {%0,%1,%2,%3};"                  \
        : "+f"(D[0]), "+f"(D[1]), "+f"(D[2]), "+f"(D[3])                         \
        : "r"(A0), "r"(A1), "r"(A2), "r"(A3), "r"(B0), "r"(B1))
                MMA_BF(s[jt],   aqh[0], aqh[1], aqh[2], aqh[3], bh0, bh1);
                MMA_BF(s[jt],   aqh[0], aqh[1], aqh[2], aqh[3], bl0, bl1);
                MMA_BF(s[jt],   aql[0], aql[1], aql[2], aql[3], bh0, bh1);
                MMA_BF(s[jt+1], aqh[0], aqh[1], aqh[2], aqh[3], bh2, bh3);
                MMA_BF(s[jt+1], aqh[0], aqh[1], aqh[2], aqh[3], bl2, bl3);
                MMA_BF(s[jt+1], aql[0], aql[1], aql[2], aql[3], bh2, bh3);
#undef MMA_BF
            }
        }

        // ---- online softmax (warp covers full j span -> warp-local) ----
        float rmax0 = -1e30f, rmax1 = -1e30f;
#pragma unroll
        for (int jt = 0; jt < 16; jt++) {
            rmax0 = fmaxf(rmax0, fmaxf(s[jt][0], s[jt][1]));
            rmax1 = fmaxf(rmax1, fmaxf(s[jt][2], s[jt][3]));
        }
        rmax0 = fmaxf(rmax0, __shfl_xor_sync(0xffffffffu, rmax0, 1));
        rmax0 = fmaxf(rmax0, __shfl_xor_sync(0xffffffffu, rmax0, 2));
        rmax1 = fmaxf(rmax1, __shfl_xor_sync(0xffffffffu, rmax1, 1));
        rmax1 = fmaxf(rmax1, __shfl_xor_sync(0xffffffffu, rmax1, 2));
        const float nm0 = fmaxf(m0, rmax0), nm1 = fmaxf(m1, rmax1);
        const float al0 = __expf(m0 - nm0), al1 = __expf(m1 - nm1);
        float sum0 = 0.0f, sum1 = 0.0f;
#pragma unroll
        for (int jt = 0; jt < 16; jt++) {
            s[jt][0] = __expf(s[jt][0] - nm0);
            s[jt][1] = __expf(s[jt][1] - nm0);
            s[jt][2] = __expf(s[jt][2] - nm1);
            s[jt][3] = __expf(s[jt][3] - nm1);
            sum0 += s[jt][0] + s[jt][1];
            sum1 += s[jt][2] + s[jt][3];
        }
        sum0 += __shfl_xor_sync(0xffffffffu, sum0, 1);
        sum0 += __shfl_xor_sync(0xffffffffu, sum0, 2);
        sum1 += __shfl_xor_sync(0xffffffffu, sum1, 1);
        sum1 += __shfl_xor_sync(0xffffffffu, sum1, 2);
        l0 = l0 * al0 + sum0;
        l1 = l1 * al1 + sum1;
        m0 = nm0; m1 = nm1;
#pragma unroll
        for (int nt = 0; nt < 16; nt++) {
            acc_o[nt][0] *= al0; acc_o[nt][1] *= al0;
            acc_o[nt][2] *= al1; acc_o[nt][3] *= al1;
        }

        asm volatile("cp.async.wait_group 0;");   // V_jb
        __syncthreads();                          // K buf free (S done by all)
        if (jb + 1 < PN / 128) {
            ldK((jb + 1) * 128);
            asm volatile("cp.async.commit_group;");
        }

        // ---- O += P Vh (fp16, 1 term); A frags packed from P regs ----
#pragma unroll
        for (int kc = 0; kc < 8; kc++) {
            __half2 t0, t1, t2, t3;
            t0.x = __float2half_rn(s[2*kc][0]);   t0.y = __float2half_rn(s[2*kc][1]);
            t1.x = __float2half_rn(s[2*kc][2]);   t1.y = __float2half_rn(s[2*kc][3]);
            t2.x = __float2half_rn(s[2*kc+1][0]); t2.y = __float2half_rn(s[2*kc+1][1]);
            t3.x = __float2half_rn(s[2*kc+1][2]); t3.y = __float2half_rn(s[2*kc+1][3]);
            uint32_t a0 = *(uint32_t*)&t0, a1 = *(uint32_t*)&t1;
            uint32_t a2 = *(uint32_t*)&t2, a3 = *(uint32_t*)&t3;
#pragma unroll
            for (int nt = 0; nt < 16; nt += 2) {
                uint32_t bh0, bh1, bh2, bh3;
                uint32_t vh_ = (uint32_t)__cvta_generic_to_shared(&vt[(nt*8 + b_row) * LDT + kc*16 + b_kh]);
                asm volatile("ldmatrix.sync.aligned.m8n8.x4.shared.b16 {%0,%1,%2,%3}, [%4];"
                    : "=r"(bh0), "=r"(bh1), "=r"(bh2), "=r"(bh3) : "r"(vh_));
#define MMA_F16(D,B0,B1)                                                          \
    asm volatile("mma.sync.aligned.m16n8k16.row.col.f32.f16.f16.f32 "            \
        "{%0,%1,%2,%3}, {%4,%5,%6,%7}, {%8,%9}, {%0,%1,%2,%3};"                  \
        : "+f"(D[0]), "+f"(D[1]), "+f"(D[2]), "+f"(D[3])                         \
        : "r"(a0), "r"(a1), "r"(a2), "r"(a3), "r"(B0), "r"(B1))
                MMA_F16(acc_o[nt],   bh0, bh1);
                MMA_F16(acc_o[nt+1], bh2, bh3);
#undef MMA_F16
            }
        }
    }

    // ---- epilogue: normalize, bf16 h/l out ----
    const int cr = lane >> 2, cc = (lane & 3) << 1;
    const float inv0 = 1.0f / l0, inv1 = 1.0f / l1;
    bf16* Oh = oh + b * qsb;
    bf16* Ol = ol + b * qsb;
    const long long r0 = i0 + wm + cr, r1 = r0 + 8;
#pragma unroll
    for (int nt = 0; nt < 16; nt++) {
        const long long col = nt*8 + cc;
        float v0 = acc_o[nt][0] * inv0, v1 = acc_o[nt][1] * inv0;
        float v2 = acc_o[nt][2] * inv1, v3 = acc_o[nt][3] * inv1;
        bf16 h0 = __float2bfloat16_rn(v0), h1 = __float2bfloat16_rn(v1);
        bf16 h2 = __float2bfloat16_rn(v2), h3 = __float2bfloat16_rn(v3);
        __nv_bfloat162 hp0; hp0.x = h0; hp0.y = h1;
        __nv_bfloat162 hp1; hp1.x = h2; hp1.y = h3;
        __nv_bfloat162 lp0, lp1;
        lp0.x = __float2bfloat16_rn(v0 - __bfloat162float(h0));
        lp0.y = __float2bfloat16_rn(v1 - __bfloat162float(h1));
        lp1.x = __float2bfloat16_rn(v2 - __bfloat162float(h2));
        lp1.y = __float2bfloat16_rn(v3 - __bfloat162float(h3));
        *(__nv_bfloat162*)&Oh[r0 * PCI + col] = hp0;
        *(__nv_bfloat162*)&Ol[r0 * PCI + col] = lp0;
        *(__nv_bfloat162*)&Oh[r1 * PCI + col] = hp1;
        *(__nv_bfloat162*)&Ol[r1 * PCI + col] = lp1;
    }
}

// ----------------------------------------------------------------------------
// Transpose + hi/lo split: src fp32 [b][R][N] -> dh/dl bf16 [b][N][R]
// ----------------------------------------------------------------------------
__global__ void __launch_bounds__(256)
tsplit(const float* __restrict__ src, bf16* __restrict__ dh, bf16* __restrict__ dl, int R)
{
    __shared__ float t[32][33];
    const int tx = threadIdx.x, ty = threadIdx.y;
    const long long b = blockIdx.z;
    const int n0 = blockIdx.x * 32, r0 = blockIdx.y * 32;
    const float* S = src + b * (long long)R * PN;
#pragma unroll
    for (int i = 0; i < 4; i++)
        t[ty + i*8][tx] = S[(long long)(r0 + ty + i*8) * PN + n0 + tx];
    __syncthreads();
    bf16* DH = dh + b * (long long)R * PN;
    bf16* DL = dl + b * (long long)R * PN;
#pragma unroll
    for (int i = 0; i < 4; i++) {
        float v = t[tx][ty + i*8];
        bf16 h = __float2bfloat16_rn(v);
        long long off = (long long)(n0 + ty + i*8) * R + r0 + tx;
        DH[off] = h;
        DL[off] = __float2bfloat16_rn(v - __bfloat162float(h));
    }
}

// Four weight splits in one launch (all 65536 elements); blockIdx.y selects.
__global__ void __launch_bounds__(256)
esplit4(const float* s0, const float* s1, const float* s2, const float* s3,
        bf16* h0, bf16* h1, bf16* h2, bf16* h3,
        bf16* l0, bf16* l1, bf16* l2, bf16* l3)
{
    const float* s; bf16* dh; bf16* dl;
    switch (blockIdx.y) {
        case 0: s = s0; dh = h0; dl = l0; break;
        case 1: s = s1; dh = h1; dl = l1; break;
        case 2: s = s2; dh = h2; dl = l2; break;
        default: s = s3; dh = h3; dl = l3; break;
    }
    int i = blockIdx.x * 256 + threadIdx.x;
    float v = s[i];
    bf16 h = __float2bfloat16_rn(v);
    dh[i] = h;
    dl[i] = __float2bfloat16_rn(v - __bfloat162float(h));
}

// ----------------------------------------------------------------------------
// Launch
// ----------------------------------------------------------------------------
extern "C" void kernel_launch(void* const* d_in, const int* in_sizes, int n_in,
                              void* d_out, int out_size)
{
    (void)in_sizes; (void)n_in; (void)out_size;
    const float* x  = (const float*)d_in[0];
    const float* wq = (const float*)d_in[1];
    const float* bq = (const float*)d_in[2];
    const float* wk = (const float*)d_in[3];
    const float* bk = (const float*)d_in[4];
    const float* wv = (const float*)d_in[5];
    const float* bv = (const float*)d_in[6];
    const float* wo = (const float*)d_in[7];
    const float* bo = (const float*)d_in[8];
    float* out = (float*)d_out;

    const int SM_P3 = 2 * (2*64  + 2*128) * 40 * 2;   // 61440
    const int SM_E  = 2 * (2*128 + 2*128) * 40 * 2;   // 81920
    const int SM_FA = 640 * LDT * 2;                  // 174080

    static bf16 *xth = nullptr, *xtl,*qh,*ql,*kh,*kl,*vh,*vl,*oh,*ol;
    static bf16 *wqh,*wql,*wkh,*wkl,*wvh,*wvl,*woh,*wol;
    if (!xth) {
        cudaGetSymbolAddress((void**)&xth, g_xth);
        cudaGetSymbolAddress((void**)&xtl, g_xtl);
        cudaGetSymbolAddress((void**)&qh,  g_qh);
        cudaGetSymbolAddress((void**)&ql,  g_ql);
        cudaGetSymbolAddress((void**)&kh,  g_kh);
        cudaGetSymbolAddress((void**)&kl,  g_kl);
        cudaGetSymbolAddress((void**)&vh,  g_vh);
        cudaGetSymbolAddress((void**)&vl,  g_vl);
        cudaGetSymbolAddress((void**)&oh,  g_oh);
        cudaGetSymbolAddress((void**)&ol,  g_ol);
        cudaGetSymbolAddress((void**)&wqh, g_wqh);
        cudaGetSymbolAddress((void**)&wql, g_wql);
        cudaGetSymbolAddress((void**)&wkh, g_wkh);
        cudaGetSymbolAddress((void**)&wkl, g_wkl);
        cudaGetSymbolAddress((void**)&wvh, g_wvh);
        cudaGetSymbolAddress((void**)&wvl, g_wvl);
        cudaGetSymbolAddress((void**)&woh, g_woh);
        cudaGetSymbolAddress((void**)&wol, g_wol);
        cudaFuncSetAttribute(mma_gemm3<64,128,32,32,1,2,3,false>,
                             cudaFuncAttributeMaxDynamicSharedMemorySize, SM_P3);
        cudaFuncSetAttribute(mma_gemm3<64,128,32,32,2,1,3,false>,
                             cudaFuncAttributeMaxDynamicSharedMemorySize, SM_P3);
        cudaFuncSetAttribute(mma_gemm3<128,128,32,64,0,1,3,false>,
                             cudaFuncAttributeMaxDynamicSharedMemorySize, SM_E);
        cudaFuncSetAttribute(flash_attn,
                             cudaFuncAttributeMaxDynamicSharedMemorySize, SM_FA);
    }

    const long long N = PN, C = PC, CI = PCI;
    const long long xsb = C * N;
    const long long tsb = N * C;
    const long long qsb = N * CI;
    const long long vsb = CI * N;
    dim3 blk(256);

    // 0) split x (transposed) + weights (one launch)
    tsplit<<<dim3(PN/32, PC/32, PB), dim3(32,8)>>>(x, xth, xtl, PC);
    esplit4<<<dim3(PCI*PC/256, 4), blk>>>(wq, wk, wv, wo,
                                          wqh, wkh, wvh, woh,
                                          wql, wkl, wvl, wol);

    // 1) q,k projections -> bf16 h/l [b][i][ci]
    mma_gemm3<64,128,32,32,1,2,3,false><<<dim3(1, PN/64, PB), blk, SM_P3>>>(
        xth, xtl, tsb, PC,  wqh, wql, 0, PC,
        nullptr, qh, ql, qsb, PCI,  bq, nullptr, 0, PC);
    mma_gemm3<64,128,32,32,1,2,3,false><<<dim3(1, PN/64, PB), blk, SM_P3>>>(
        xth, xtl, tsb, PC,  wkh, wkl, 0, PC,
        nullptr, kh, kl, qsb, PCI,  bk, nullptr, 0, PC);

    // 2) v projection -> fp16 h/l [b][ci][j]
    mma_gemm3<64,128,32,32,2,1,3,false><<<dim3(PN/128, PCI/64, PB), blk, SM_P3>>>(
        wvh, wvl, 0, PC,  xth, xtl, tsb, PC,
        nullptr, vh, vl, vsb, PN,  bv, nullptr, 0, PC);

    // 3) fused attention: energy + softmax + PV -> oh/ol bf16 h/l [b][i][ci]
    flash_attn<<<dim3(PN/128, PB), blk, SM_FA>>>(qh, ql, kh, kl, vh, oh, ol);

    // 4) out = wo * O^T + bo + x -> fp32 d_out
    mma_gemm3<128,128,32,64,0,1,3,false><<<dim3(PN/128, PC/128, PB), blk, SM_E>>>(
        woh, wol, 0, PCI,  oh, ol, qsb, PCI,
        out, nullptr, nullptr, xsb, PN,  bo, x, xsb, PCI);
}